// round 2
// baseline (speedup 1.0000x reference)
#include <cuda_runtime.h>
#include <math.h>

#define S_LEN 2048
#define B_SZ 2
#define D_MODEL 2048
#define NH 16
#define HD 128
#define MROWS (B_SZ * S_LEN)   // 4096

// ---------------- scratch (static device allocations: allowed) ----------------
__device__ float g_q[(size_t)B_SZ * S_LEN * D_MODEL];
__device__ float g_k[(size_t)B_SZ * S_LEN * D_MODEL];
__device__ float g_v[(size_t)B_SZ * S_LEN * D_MODEL];
__device__ float g_o[(size_t)B_SZ * S_LEN * D_MODEL];
__device__ float g_cos[S_LEN * (HD / 2)];
__device__ float g_sin[S_LEN * (HD / 2)];

// ---------------- RoPE table (double precision angles) ----------------
__global__ void rope_table_kernel() {
    int idx = blockIdx.x * blockDim.x + threadIdx.x;
    if (idx >= S_LEN * (HD / 2)) return;
    int s = idx >> 6;          // HD/2 = 64
    int i = idx & 63;
    double freq = exp(-log(10000.0) * (double)(2 * i) / (double)HD);
    double ang = (double)s * freq;
    g_cos[idx] = (float)cos(ang);
    g_sin[idx] = (float)sin(ang);
}

// ---------------- RoPE apply (in-place on q or k, interleaved pairs) ----------
__global__ void rope_apply_kernel(float* __restrict__ t) {
    const int NP = B_SZ * S_LEN * D_MODEL / 2;
    int idx = blockIdx.x * blockDim.x + threadIdx.x;   // pair index
    if (idx >= NP) return;
    int d2 = idx & (D_MODEL / 2 - 1);          // pair index within row
    int s  = (idx / (D_MODEL / 2)) & (S_LEN - 1);
    int i  = d2 & 63;                          // pair index within head
    float c  = g_cos[(s << 6) + i];
    float sn = g_sin[(s << 6) + i];
    float2 v = *(float2*)(t + 2 * (size_t)idx);
    float r0 = v.x * c - v.y * sn;
    float r1 = v.x * sn + v.y * c;
    *(float2*)(t + 2 * (size_t)idx) = make_float2(r0, r1);
}

// ---------------- SGEMM: C[M,N] = A[M,K] @ B[N,K]^T (both K-major) -----------
#define BM 128
#define BN 128
#define BK 16

__global__ __launch_bounds__(256) void sgemm_nt(
    const float* __restrict__ A, const float* __restrict__ B,
    float* __restrict__ C, int M, int N, int K)
{
    __shared__ float As[BK][BM];
    __shared__ float Bs[BK][BN];

    int tid = threadIdx.x;
    int tx = tid & 15;          // n-dim thread coord
    int ty = tid >> 4;          // m-dim thread coord
    int m0 = blockIdx.y * BM;
    int n0 = blockIdx.x * BN;

    float acc[8][8];
#pragma unroll
    for (int i = 0; i < 8; i++)
#pragma unroll
        for (int j = 0; j < 8; j++) acc[i][j] = 0.f;

    for (int kt = 0; kt < K; kt += BK) {
#pragma unroll
        for (int l = 0; l < 2; l++) {
            int i4 = tid + l * 256;
            int r  = i4 >> 2;
            int c4 = (i4 & 3) * 4;
            float4 av = *(const float4*)(A + (size_t)(m0 + r) * K + kt + c4);
            As[c4 + 0][r] = av.x; As[c4 + 1][r] = av.y;
            As[c4 + 2][r] = av.z; As[c4 + 3][r] = av.w;
            float4 bv = *(const float4*)(B + (size_t)(n0 + r) * K + kt + c4);
            Bs[c4 + 0][r] = bv.x; Bs[c4 + 1][r] = bv.y;
            Bs[c4 + 2][r] = bv.z; Bs[c4 + 3][r] = bv.w;
        }
        __syncthreads();

#pragma unroll
        for (int kk = 0; kk < BK; kk++) {
            float a[8], b[8];
            *(float4*)&a[0] = *(const float4*)&As[kk][ty * 4];
            *(float4*)&a[4] = *(const float4*)&As[kk][64 + ty * 4];
            *(float4*)&b[0] = *(const float4*)&Bs[kk][tx * 4];
            *(float4*)&b[4] = *(const float4*)&Bs[kk][64 + tx * 4];
#pragma unroll
            for (int i = 0; i < 8; i++)
#pragma unroll
                for (int j = 0; j < 8; j++)
                    acc[i][j] += a[i] * b[j];
        }
        __syncthreads();
    }

#pragma unroll
    for (int i = 0; i < 8; i++) {
        int r = m0 + ((i < 4) ? (ty * 4 + i) : (64 + ty * 4 + i - 4));
        float4 v0 = make_float4(acc[i][0], acc[i][1], acc[i][2], acc[i][3]);
        float4 v1 = make_float4(acc[i][4], acc[i][5], acc[i][6], acc[i][7]);
        *(float4*)(C + (size_t)r * N + n0 + tx * 4)      = v0;
        *(float4*)(C + (size_t)r * N + n0 + 64 + tx * 4) = v1;
    }
}

// ---------------- Flash attention (causal, fp32, hd=128) ---------------------
#define AQ 64
#define AK 64
#define KPAD 132
#define SPAD 65
// smem floats: Qs 64*128 + Ks 64*132 + Vs 64*128 + Ss 64*65
#define SMEM_ATTN_FLOATS (AQ * HD + AK * KPAD + AK * HD + AQ * SPAD)
#define SMEM_ATTN_BYTES  (SMEM_ATTN_FLOATS * 4)

__global__ __launch_bounds__(256) void flash_attn_kernel() {
    extern __shared__ float sm[];
    float (*Qs)[HD]   = (float(*)[HD])sm;
    float (*Ks)[KPAD] = (float(*)[KPAD])(sm + AQ * HD);
    float (*Vs)[HD]   = (float(*)[HD])(sm + AQ * HD + AK * KPAD);
    float (*Ss)[SPAD] = (float(*)[SPAD])(sm + AQ * HD + AK * KPAD + AK * HD);

    int tid = threadIdx.x;
    int tx = tid & 15;       // 16 col-threads
    int ty = tid >> 4;       // 16 row-threads
    int qt = blockIdx.x;
    int bh = blockIdx.y;
    int b = bh >> 4;
    int h = bh & 15;
    int q0 = qt * AQ;

    const float* qp = g_q + (size_t)b * S_LEN * D_MODEL + (size_t)h * HD;
    const float* kp = g_k + (size_t)b * S_LEN * D_MODEL + (size_t)h * HD;
    const float* vp = g_v + (size_t)b * S_LEN * D_MODEL + (size_t)h * HD;
    float*       op = g_o + (size_t)b * S_LEN * D_MODEL + (size_t)h * HD;

    // load Q tile [64][128]
#pragma unroll
    for (int l = 0; l < 8; l++) {
        int i4 = tid + l * 256;
        int r  = i4 >> 5;
        int c  = (i4 & 31) * 4;
        *(float4*)&Qs[r][c] = *(const float4*)(qp + (size_t)(q0 + r) * D_MODEL + c);
    }

    float m_i[4], l_i[4], acc[4][8];
#pragma unroll
    for (int i = 0; i < 4; i++) {
        m_i[i] = -1e30f;
        l_i[i] = 0.f;
#pragma unroll
        for (int d = 0; d < 8; d++) acc[i][d] = 0.f;
    }

    const float sm_scale = 0.08838834764831843f;  // 1/sqrt(128)

    for (int kt = 0; kt <= qt; kt++) {
        int k0 = kt * AK;
        __syncthreads();
#pragma unroll
        for (int l = 0; l < 8; l++) {
            int i4 = tid + l * 256;
            int r  = i4 >> 5;
            int c  = (i4 & 31) * 4;
            *(float4*)&Ks[r][c] = *(const float4*)(kp + (size_t)(k0 + r) * D_MODEL + c);
            *(float4*)&Vs[r][c] = *(const float4*)(vp + (size_t)(k0 + r) * D_MODEL + c);
        }
        __syncthreads();

        // scores 4x4 per thread
        float s[4][4];
#pragma unroll
        for (int i = 0; i < 4; i++)
#pragma unroll
            for (int j = 0; j < 4; j++) s[i][j] = 0.f;

#pragma unroll 8
        for (int kk = 0; kk < HD; kk += 4) {
            float4 qv[4], kv[4];
#pragma unroll
            for (int i = 0; i < 4; i++) qv[i] = *(const float4*)&Qs[ty * 4 + i][kk];
#pragma unroll
            for (int j = 0; j < 4; j++) kv[j] = *(const float4*)&Ks[tx * 4 + j][kk];
#pragma unroll
            for (int i = 0; i < 4; i++)
#pragma unroll
                for (int j = 0; j < 4; j++) {
                    s[i][j] += qv[i].x * kv[j].x + qv[i].y * kv[j].y
                             + qv[i].z * kv[j].z + qv[i].w * kv[j].w;
                }
        }

#pragma unroll
        for (int i = 0; i < 4; i++)
#pragma unroll
            for (int j = 0; j < 4; j++) s[i][j] *= sm_scale;

        if (kt == qt) {
#pragma unroll
            for (int i = 0; i < 4; i++)
#pragma unroll
                for (int j = 0; j < 4; j++)
                    if (k0 + tx * 4 + j > q0 + ty * 4 + i) s[i][j] = -1e30f;
        }

        // online softmax update per row
#pragma unroll
        for (int i = 0; i < 4; i++) {
            float rm = fmaxf(fmaxf(s[i][0], s[i][1]), fmaxf(s[i][2], s[i][3]));
            rm = fmaxf(rm, __shfl_xor_sync(0xffffffffu, rm, 1));
            rm = fmaxf(rm, __shfl_xor_sync(0xffffffffu, rm, 2));
            rm = fmaxf(rm, __shfl_xor_sync(0xffffffffu, rm, 4));
            rm = fmaxf(rm, __shfl_xor_sync(0xffffffffu, rm, 8));
            float mnew = fmaxf(m_i[i], rm);
            float rs = 0.f;
#pragma unroll
            for (int j = 0; j < 4; j++) {
                float p = expf(s[i][j] - mnew);
                rs += p;
                Ss[ty * 4 + i][tx * 4 + j] = p;
            }
            rs += __shfl_xor_sync(0xffffffffu, rs, 1);
            rs += __shfl_xor_sync(0xffffffffu, rs, 2);
            rs += __shfl_xor_sync(0xffffffffu, rs, 4);
            rs += __shfl_xor_sync(0xffffffffu, rs, 8);
            float alpha = expf(m_i[i] - mnew);
            l_i[i] = l_i[i] * alpha + rs;
            m_i[i] = mnew;
#pragma unroll
            for (int d = 0; d < 8; d++) acc[i][d] *= alpha;
        }
        __syncthreads();

        // PV: acc[i][*] += P[row][j] * V[j][*]
#pragma unroll 4
        for (int j = 0; j < AK; j++) {
            float4 v0 = *(const float4*)&Vs[j][tx * 4];
            float4 v1 = *(const float4*)&Vs[j][64 + tx * 4];
#pragma unroll
            for (int i = 0; i < 4; i++) {
                float pij = Ss[ty * 4 + i][j];
                acc[i][0] += pij * v0.x; acc[i][1] += pij * v0.y;
                acc[i][2] += pij * v0.z; acc[i][3] += pij * v0.w;
                acc[i][4] += pij * v1.x; acc[i][5] += pij * v1.y;
                acc[i][6] += pij * v1.z; acc[i][7] += pij * v1.w;
            }
        }
    }

    // epilogue: normalize and store
#pragma unroll
    for (int i = 0; i < 4; i++) {
        float inv = 1.f / l_i[i];
        int r = q0 + ty * 4 + i;
        float4 v0 = make_float4(acc[i][0] * inv, acc[i][1] * inv,
                                acc[i][2] * inv, acc[i][3] * inv);
        float4 v1 = make_float4(acc[i][4] * inv, acc[i][5] * inv,
                                acc[i][6] * inv, acc[i][7] * inv);
        *(float4*)(op + (size_t)r * D_MODEL + tx * 4)      = v0;
        *(float4*)(op + (size_t)r * D_MODEL + 64 + tx * 4) = v1;
    }
}

// ---------------- launch ----------------
extern "C" void kernel_launch(void* const* d_in, const int* in_sizes, int n_in,
                              void* d_out, int out_size) {
    const float* x  = (const float*)d_in[0];
    const float* wq = (const float*)d_in[1];
    const float* wk = (const float*)d_in[2];
    const float* wv = (const float*)d_in[3];
    const float* wo = (const float*)d_in[4];
    float* out = (float*)d_out;

    float *q, *k, *v, *o;
    cudaGetSymbolAddress((void**)&q, g_q);
    cudaGetSymbolAddress((void**)&k, g_k);
    cudaGetSymbolAddress((void**)&v, g_v);
    cudaGetSymbolAddress((void**)&o, g_o);

    rope_table_kernel<<<(S_LEN * (HD / 2) + 255) / 256, 256>>>();

    dim3 gg(D_MODEL / BN, MROWS / BM);
    sgemm_nt<<<gg, 256>>>(x, wq, q, MROWS, D_MODEL, D_MODEL);
    sgemm_nt<<<gg, 256>>>(x, wk, k, MROWS, D_MODEL, D_MODEL);
    sgemm_nt<<<gg, 256>>>(x, wv, v, MROWS, D_MODEL, D_MODEL);

    const int np = B_SZ * S_LEN * D_MODEL / 2;
    rope_apply_kernel<<<(np + 255) / 256, 256>>>(q);
    rope_apply_kernel<<<(np + 255) / 256, 256>>>(k);

    cudaFuncSetAttribute(flash_attn_kernel,
                         cudaFuncAttributeMaxDynamicSharedMemorySize,
                         SMEM_ATTN_BYTES);
    flash_attn_kernel<<<dim3(S_LEN / AQ, B_SZ * NH), 256, SMEM_ATTN_BYTES>>>();

    sgemm_nt<<<gg, 256>>>(o, wo, out, MROWS, D_MODEL, D_MODEL);
}

// round 5
// speedup vs baseline: 1.5642x; 1.5642x over previous
#include <cuda_runtime.h>
#include <cuda_bf16.h>
#include <stdint.h>
#include <math.h>

#define S_LEN 2048
#define B_SZ 2
#define D_MODEL 2048
#define NH 16
#define HD 128
#define MROWS (B_SZ * S_LEN)
#define KDIM 2048

// ---------------- scratch (static device allocations: allowed) ----------------
__device__ float g_q[(size_t)B_SZ * S_LEN * D_MODEL];
__device__ float g_k[(size_t)B_SZ * S_LEN * D_MODEL];
__device__ float g_v[(size_t)B_SZ * S_LEN * D_MODEL];
__device__ float g_o[(size_t)B_SZ * S_LEN * D_MODEL];
__device__ float g_cos[S_LEN * (HD / 2)];
__device__ float g_sin[S_LEN * (HD / 2)];

__device__ __nv_bfloat16 g_xhi[(size_t)MROWS * D_MODEL];
__device__ __nv_bfloat16 g_xlo[(size_t)MROWS * D_MODEL];
__device__ __nv_bfloat16 g_ohi[(size_t)MROWS * D_MODEL];
__device__ __nv_bfloat16 g_olo[(size_t)MROWS * D_MODEL];
__device__ __nv_bfloat16 g_wqhi[(size_t)D_MODEL * D_MODEL];
__device__ __nv_bfloat16 g_wqlo[(size_t)D_MODEL * D_MODEL];
__device__ __nv_bfloat16 g_wkhi[(size_t)D_MODEL * D_MODEL];
__device__ __nv_bfloat16 g_wklo[(size_t)D_MODEL * D_MODEL];
__device__ __nv_bfloat16 g_wvhi[(size_t)D_MODEL * D_MODEL];
__device__ __nv_bfloat16 g_wvlo[(size_t)D_MODEL * D_MODEL];
__device__ __nv_bfloat16 g_wohi[(size_t)D_MODEL * D_MODEL];
__device__ __nv_bfloat16 g_wolo[(size_t)D_MODEL * D_MODEL];

// ======================= low-level helpers (plain C, no templates/lambdas) ====
__device__ __forceinline__ uint32_t smem_u32(const void* p) {
    uint32_t a;
    asm("{ .reg .u64 t; cvta.to.shared.u64 t, %1; cvt.u32.u64 %0, t; }" : "=r"(a) : "l"(p));
    return a;
}
__device__ __forceinline__ void cp16(uint32_t dst, const void* src) {
    asm volatile("cp.async.cg.shared.global [%0], [%1], 16;" :: "r"(dst), "l"(src));
}
__device__ __forceinline__ void cp_commit() {
    asm volatile("cp.async.commit_group;" ::: "memory");
}
#define CP_WAIT(n) asm volatile("cp.async.wait_group " #n ";" ::: "memory")

__device__ __forceinline__ void ldsm_x4(uint32_t* r, uint32_t addr) {
    asm volatile("ldmatrix.sync.aligned.m8n8.x4.shared.b16 {%0,%1,%2,%3}, [%4];"
                 : "=r"(r[0]), "=r"(r[1]), "=r"(r[2]), "=r"(r[3]) : "r"(addr));
}
__device__ __forceinline__ void mma_bf16(float* d, const uint32_t* a, const uint32_t* b) {
    asm volatile(
        "mma.sync.aligned.m16n8k16.row.col.f32.bf16.bf16.f32 "
        "{%0,%1,%2,%3}, {%4,%5,%6,%7}, {%8,%9}, {%0,%1,%2,%3};"
        : "+f"(d[0]), "+f"(d[1]), "+f"(d[2]), "+f"(d[3])
        : "r"(a[0]), "r"(a[1]), "r"(a[2]), "r"(a[3]), "r"(b[0]), "r"(b[1]));
}

// SW128 swizzle on byte offsets within a [rows][128B] tile
#define SWZ(x) ((x) ^ (((x) >> 3) & 0x70))

// ======================= bf16x3 tensor-core GEMM (mma.sync) ==================
#define GBM 128
#define GBN 128
#define NCHUNK (KDIM / 64)
#define TILE_B (GBM * 128)
#define STAGE_B (4 * TILE_B)
#define GEMM_SMEM (2 * STAGE_B)

__device__ __forceinline__ void gemm_issue(
    const __nv_bfloat16* Ah, const __nv_bfloat16* Al,
    const __nv_bfloat16* Bh, const __nv_bfloat16* Bl,
    uint32_t sb0, int m0, int n0, int tid, int c, int s)
{
    const uint32_t st = sb0 + (uint32_t)s * STAGE_B;
    const size_t kb = (size_t)c * 128;
    const int lq = tid & 7;
#pragma unroll
    for (int i = 0; i < 4; i++) {
        const int r = (tid + i * 256) >> 3;
        const uint32_t dsw = SWZ((uint32_t)(r * 128 + lq * 16));
        const size_t arow = (size_t)(m0 + r) * (KDIM * 2) + kb + (size_t)lq * 16;
        const size_t brow = (size_t)(n0 + r) * (KDIM * 2) + kb + (size_t)lq * 16;
        cp16(st + dsw,              (const char*)Ah + arow);
        cp16(st + TILE_B + dsw,     (const char*)Al + arow);
        cp16(st + 2 * TILE_B + dsw, (const char*)Bh + brow);
        cp16(st + 3 * TILE_B + dsw, (const char*)Bl + brow);
    }
    cp_commit();
}

__global__ __launch_bounds__(256) void gemm_mma_bf16x3(
    const __nv_bfloat16* __restrict__ Ah, const __nv_bfloat16* __restrict__ Al,
    const __nv_bfloat16* __restrict__ Bh, const __nv_bfloat16* __restrict__ Bl,
    float* __restrict__ C)
{
    extern __shared__ char smem[];
    const uint32_t sb0 = smem_u32(smem);

    const int tid = threadIdx.x;
    const int wid = tid >> 5;
    const int lane = tid & 31;
    const int wm = wid >> 2;
    const int wn = wid & 3;
    const int m_base = wm * 64;
    const int n_base = wn * 32;
    const int m0 = blockIdx.y * GBM;
    const int n0 = blockIdx.x * GBN;

    float acc[4][4][4];
#pragma unroll
    for (int i = 0; i < 4; i++) {
#pragma unroll
        for (int j = 0; j < 4; j++) {
#pragma unroll
            for (int e = 0; e < 4; e++) { acc[i][j][e] = 0.f; }
        }
    }

    gemm_issue(Ah, Al, Bh, Bl, sb0, m0, n0, tid, 0, 0);
    gemm_issue(Ah, Al, Bh, Bl, sb0, m0, n0, tid, 1, 1);

    const int g8 = lane >> 3;
    const int r8 = lane & 7;
    const int rowoff = (g8 & 1) * 8 + r8;
    const int qhi = g8 >> 1;

    for (int c = 0; c < NCHUNK; c++) {
        const int s = c & 1;
        CP_WAIT(1);
        __syncthreads();
        const uint32_t sAh = sb0 + (uint32_t)s * STAGE_B;
        const uint32_t sAl = sAh + TILE_B;
        const uint32_t sBh = sAh + 2 * TILE_B;
        const uint32_t sBl = sAh + 3 * TILE_B;

#pragma unroll
        for (int ks = 0; ks < 4; ks++) {
            const int quad = ks * 2 + qhi;
            uint32_t ah[4][4], al[4][4], bh[4][2], bl[4][2];
#pragma unroll
            for (int mi = 0; mi < 4; mi++) {
                const uint32_t off = SWZ((uint32_t)((m_base + mi * 16 + rowoff) * 128 + quad * 16));
                ldsm_x4(ah[mi], sAh + off);
                ldsm_x4(al[mi], sAl + off);
            }
#pragma unroll
            for (int p = 0; p < 2; p++) {
                const uint32_t off = SWZ((uint32_t)((n_base + p * 16 + rowoff) * 128 + quad * 16));
                uint32_t t[4];
                ldsm_x4(t, sBh + off);
                bh[2 * p][0] = t[0]; bh[2 * p][1] = t[2];
                bh[2 * p + 1][0] = t[1]; bh[2 * p + 1][1] = t[3];
                ldsm_x4(t, sBl + off);
                bl[2 * p][0] = t[0]; bl[2 * p][1] = t[2];
                bl[2 * p + 1][0] = t[1]; bl[2 * p + 1][1] = t[3];
            }
#pragma unroll
            for (int mi = 0; mi < 4; mi++) {
#pragma unroll
                for (int ni = 0; ni < 4; ni++) {
                    mma_bf16(acc[mi][ni], ah[mi], bh[ni]);
                    mma_bf16(acc[mi][ni], ah[mi], bl[ni]);
                    mma_bf16(acc[mi][ni], al[mi], bh[ni]);
                }
            }
        }
        __syncthreads();
        if (c + 2 < NCHUNK) {
            gemm_issue(Ah, Al, Bh, Bl, sb0, m0, n0, tid, c + 2, s);
        }
    }

    const int erow = lane >> 2;
    const int ecol = (lane & 3) * 2;
#pragma unroll
    for (int mi = 0; mi < 4; mi++) {
#pragma unroll
        for (int ni = 0; ni < 4; ni++) {
            const int row = m0 + m_base + mi * 16 + erow;
            const int col = n0 + n_base + ni * 8 + ecol;
            *(float2*)(C + (size_t)row * D_MODEL + col) =
                make_float2(acc[mi][ni][0], acc[mi][ni][1]);
            *(float2*)(C + (size_t)(row + 8) * D_MODEL + col) =
                make_float2(acc[mi][ni][2], acc[mi][ni][3]);
        }
    }
}

// ---------------- fp32 -> (hi, lo) bf16 split ----------------
__global__ void split_bf16_kernel(const float* __restrict__ src,
                                  __nv_bfloat16* __restrict__ hi,
                                  __nv_bfloat16* __restrict__ lo, int n4)
{
    int i = blockIdx.x * blockDim.x + threadIdx.x;
    if (i >= n4) return;
    float4 f = ((const float4*)src)[i];
    __nv_bfloat16 h0 = __float2bfloat16(f.x);
    __nv_bfloat16 h1 = __float2bfloat16(f.y);
    __nv_bfloat16 h2 = __float2bfloat16(f.z);
    __nv_bfloat16 h3 = __float2bfloat16(f.w);
    __nv_bfloat16 l0 = __float2bfloat16(f.x - __bfloat162float(h0));
    __nv_bfloat16 l1 = __float2bfloat16(f.y - __bfloat162float(h1));
    __nv_bfloat16 l2 = __float2bfloat16(f.z - __bfloat162float(h2));
    __nv_bfloat16 l3 = __float2bfloat16(f.w - __bfloat162float(h3));
    ushort4 hv, lv;
    hv.x = __bfloat16_as_ushort(h0); hv.y = __bfloat16_as_ushort(h1);
    hv.z = __bfloat16_as_ushort(h2); hv.w = __bfloat16_as_ushort(h3);
    lv.x = __bfloat16_as_ushort(l0); lv.y = __bfloat16_as_ushort(l1);
    lv.z = __bfloat16_as_ushort(l2); lv.w = __bfloat16_as_ushort(l3);
    ((ushort4*)hi)[i] = hv;
    ((ushort4*)lo)[i] = lv;
}

// ---------------- RoPE table (double precision angles) ----------------
__global__ void rope_table_kernel() {
    int idx = blockIdx.x * blockDim.x + threadIdx.x;
    if (idx >= S_LEN * (HD / 2)) return;
    int s = idx >> 6;
    int i = idx & 63;
    double freq = exp(-log(10000.0) * (double)(2 * i) / (double)HD);
    double ang = (double)s * freq;
    g_cos[idx] = (float)cos(ang);
    g_sin[idx] = (float)sin(ang);
}

// ---------------- RoPE apply (in-place on q or k, interleaved pairs) ----------
__global__ void rope_apply_kernel(float* __restrict__ t) {
    const int NP = B_SZ * S_LEN * D_MODEL / 2;
    int idx = blockIdx.x * blockDim.x + threadIdx.x;
    if (idx >= NP) return;
    int d2 = idx & (D_MODEL / 2 - 1);
    int s  = (idx / (D_MODEL / 2)) & (S_LEN - 1);
    int i  = d2 & 63;
    float c  = g_cos[(s << 6) + i];
    float sn = g_sin[(s << 6) + i];
    float2 v = *(float2*)(t + 2 * (size_t)idx);
    float r0 = v.x * c - v.y * sn;
    float r1 = v.x * sn + v.y * c;
    *(float2*)(t + 2 * (size_t)idx) = make_float2(r0, r1);
}

// ---------------- Flash attention (causal, fp32, hd=128) ---------------------
#define AQ 64
#define AK 64
#define KPAD 132
#define SPAD 65
#define SMEM_ATTN_FLOATS (AQ * HD + AK * KPAD + AK * HD + AQ * SPAD)
#define SMEM_ATTN_BYTES  (SMEM_ATTN_FLOATS * 4)

__global__ __launch_bounds__(256) void flash_attn_kernel() {
    extern __shared__ float smf[];
    float (*Qs)[HD]   = (float(*)[HD])smf;
    float (*Ks)[KPAD] = (float(*)[KPAD])(smf + AQ * HD);
    float (*Vs)[HD]   = (float(*)[HD])(smf + AQ * HD + AK * KPAD);
    float (*Ss)[SPAD] = (float(*)[SPAD])(smf + AQ * HD + AK * KPAD + AK * HD);

    int tid = threadIdx.x;
    int tx = tid & 15;
    int ty = tid >> 4;
    int qt = blockIdx.x;
    int bh = blockIdx.y;
    int b = bh >> 4;
    int h = bh & 15;
    int q0 = qt * AQ;

    const float* qp = g_q + (size_t)b * S_LEN * D_MODEL + (size_t)h * HD;
    const float* kp = g_k + (size_t)b * S_LEN * D_MODEL + (size_t)h * HD;
    const float* vp = g_v + (size_t)b * S_LEN * D_MODEL + (size_t)h * HD;
    float*       op = g_o + (size_t)b * S_LEN * D_MODEL + (size_t)h * HD;

#pragma unroll
    for (int l = 0; l < 8; l++) {
        int i4 = tid + l * 256;
        int r  = i4 >> 5;
        int c  = (i4 & 31) * 4;
        *(float4*)&Qs[r][c] = *(const float4*)(qp + (size_t)(q0 + r) * D_MODEL + c);
    }

    float m_i[4], l_i[4], acc[4][8];
#pragma unroll
    for (int i = 0; i < 4; i++) {
        m_i[i] = -1e30f;
        l_i[i] = 0.f;
#pragma unroll
        for (int d = 0; d < 8; d++) { acc[i][d] = 0.f; }
    }

    const float sm_scale = 0.08838834764831843f;

    for (int kt = 0; kt <= qt; kt++) {
        int k0 = kt * AK;
        __syncthreads();
#pragma unroll
        for (int l = 0; l < 8; l++) {
            int i4 = tid + l * 256;
            int r  = i4 >> 5;
            int c  = (i4 & 31) * 4;
            *(float4*)&Ks[r][c] = *(const float4*)(kp + (size_t)(k0 + r) * D_MODEL + c);
            *(float4*)&Vs[r][c] = *(const float4*)(vp + (size_t)(k0 + r) * D_MODEL + c);
        }
        __syncthreads();

        float s[4][4];
#pragma unroll
        for (int i = 0; i < 4; i++) {
#pragma unroll
            for (int j = 0; j < 4; j++) { s[i][j] = 0.f; }
        }

#pragma unroll 8
        for (int kk = 0; kk < HD; kk += 4) {
            float4 qv[4], kv[4];
#pragma unroll
            for (int i = 0; i < 4; i++) { qv[i] = *(const float4*)&Qs[ty * 4 + i][kk]; }
#pragma unroll
            for (int j = 0; j < 4; j++) { kv[j] = *(const float4*)&Ks[tx * 4 + j][kk]; }
#pragma unroll
            for (int i = 0; i < 4; i++) {
#pragma unroll
                for (int j = 0; j < 4; j++) {
                    s[i][j] += qv[i].x * kv[j].x + qv[i].y * kv[j].y
                             + qv[i].z * kv[j].z + qv[i].w * kv[j].w;
                }
            }
        }

#pragma unroll
        for (int i = 0; i < 4; i++) {
#pragma unroll
            for (int j = 0; j < 4; j++) { s[i][j] *= sm_scale; }
        }

        if (kt == qt) {
#pragma unroll
            for (int i = 0; i < 4; i++) {
#pragma unroll
                for (int j = 0; j < 4; j++) {
                    if (k0 + tx * 4 + j > q0 + ty * 4 + i) { s[i][j] = -1e30f; }
                }
            }
        }

#pragma unroll
        for (int i = 0; i < 4; i++) {
            float rm = fmaxf(fmaxf(s[i][0], s[i][1]), fmaxf(s[i][2], s[i][3]));
            rm = fmaxf(rm, __shfl_xor_sync(0xffffffffu, rm, 1));
            rm = fmaxf(rm, __shfl_xor_sync(0xffffffffu, rm, 2));
            rm = fmaxf(rm, __shfl_xor_sync(0xffffffffu, rm, 4));
            rm = fmaxf(rm, __shfl_xor_sync(0xffffffffu, rm, 8));
            float mnew = fmaxf(m_i[i], rm);
            float rs = 0.f;
#pragma unroll
            for (int j = 0; j < 4; j++) {
                float p = expf(s[i][j] - mnew);
                rs += p;
                Ss[ty * 4 + i][tx * 4 + j] = p;
            }
            rs += __shfl_xor_sync(0xffffffffu, rs, 1);
            rs += __shfl_xor_sync(0xffffffffu, rs, 2);
            rs += __shfl_xor_sync(0xffffffffu, rs, 4);
            rs += __shfl_xor_sync(0xffffffffu, rs, 8);
            float alpha = expf(m_i[i] - mnew);
            l_i[i] = l_i[i] * alpha + rs;
            m_i[i] = mnew;
#pragma unroll
            for (int d = 0; d < 8; d++) { acc[i][d] *= alpha; }
        }
        __syncthreads();

#pragma unroll 4
        for (int j = 0; j < AK; j++) {
            float4 v0 = *(const float4*)&Vs[j][tx * 4];
            float4 v1 = *(const float4*)&Vs[j][64 + tx * 4];
#pragma unroll
            for (int i = 0; i < 4; i++) {
                float pij = Ss[ty * 4 + i][j];
                acc[i][0] += pij * v0.x; acc[i][1] += pij * v0.y;
                acc[i][2] += pij * v0.z; acc[i][3] += pij * v0.w;
                acc[i][4] += pij * v1.x; acc[i][5] += pij * v1.y;
                acc[i][6] += pij * v1.z; acc[i][7] += pij * v1.w;
            }
        }
    }

#pragma unroll
    for (int i = 0; i < 4; i++) {
        float inv = 1.f / l_i[i];
        int r = q0 + ty * 4 + i;
        float4 v0 = make_float4(acc[i][0] * inv, acc[i][1] * inv,
                                acc[i][2] * inv, acc[i][3] * inv);
        float4 v1 = make_float4(acc[i][4] * inv, acc[i][5] * inv,
                                acc[i][6] * inv, acc[i][7] * inv);
        *(float4*)(op + (size_t)r * D_MODEL + tx * 4)      = v0;
        *(float4*)(op + (size_t)r * D_MODEL + 64 + tx * 4) = v1;
    }
}

// ======================= host side =======================
extern "C" void kernel_launch(void* const* d_in, const int* in_sizes, int n_in,
                              void* d_out, int out_size) {
    const float* x  = (const float*)d_in[0];
    const float* wq = (const float*)d_in[1];
    const float* wk = (const float*)d_in[2];
    const float* wv = (const float*)d_in[3];
    const float* wo = (const float*)d_in[4];
    float* out = (float*)d_out;

    float *q, *k, *v, *o;
    cudaGetSymbolAddress((void**)&q, g_q);
    cudaGetSymbolAddress((void**)&k, g_k);
    cudaGetSymbolAddress((void**)&v, g_v);
    cudaGetSymbolAddress((void**)&o, g_o);

    __nv_bfloat16 *xhi, *xlo, *ohi, *olo;
    __nv_bfloat16 *wqhi, *wqlo, *wkhi, *wklo, *wvhi, *wvlo, *wohi, *wolo;
    cudaGetSymbolAddress((void**)&xhi, g_xhi);  cudaGetSymbolAddress((void**)&xlo, g_xlo);
    cudaGetSymbolAddress((void**)&ohi, g_ohi);  cudaGetSymbolAddress((void**)&olo, g_olo);
    cudaGetSymbolAddress((void**)&wqhi, g_wqhi); cudaGetSymbolAddress((void**)&wqlo, g_wqlo);
    cudaGetSymbolAddress((void**)&wkhi, g_wkhi); cudaGetSymbolAddress((void**)&wklo, g_wklo);
    cudaGetSymbolAddress((void**)&wvhi, g_wvhi); cudaGetSymbolAddress((void**)&wvlo, g_wvlo);
    cudaGetSymbolAddress((void**)&wohi, g_wohi); cudaGetSymbolAddress((void**)&wolo, g_wolo);

    rope_table_kernel<<<(S_LEN * (HD / 2) + 255) / 256, 256>>>();

    const int xn4 = MROWS * D_MODEL / 4;
    const int wn4 = D_MODEL * D_MODEL / 4;
    split_bf16_kernel<<<(xn4 + 255) / 256, 256>>>(x, xhi, xlo, xn4);
    split_bf16_kernel<<<(wn4 + 255) / 256, 256>>>(wq, wqhi, wqlo, wn4);
    split_bf16_kernel<<<(wn4 + 255) / 256, 256>>>(wk, wkhi, wklo, wn4);
    split_bf16_kernel<<<(wn4 + 255) / 256, 256>>>(wv, wvhi, wvlo, wn4);
    split_bf16_kernel<<<(wn4 + 255) / 256, 256>>>(wo, wohi, wolo, wn4);

    cudaFuncSetAttribute(gemm_mma_bf16x3, cudaFuncAttributeMaxDynamicSharedMemorySize, GEMM_SMEM);
    dim3 gg(D_MODEL / GBN, MROWS / GBM);
    gemm_mma_bf16x3<<<gg, 256, GEMM_SMEM>>>(xhi, xlo, wqhi, wqlo, q);
    gemm_mma_bf16x3<<<gg, 256, GEMM_SMEM>>>(xhi, xlo, wkhi, wklo, k);
    gemm_mma_bf16x3<<<gg, 256, GEMM_SMEM>>>(xhi, xlo, wvhi, wvlo, v);

    const int np = B_SZ * S_LEN * D_MODEL / 2;
    rope_apply_kernel<<<(np + 255) / 256, 256>>>(q);
    rope_apply_kernel<<<(np + 255) / 256, 256>>>(k);

    cudaFuncSetAttribute(flash_attn_kernel,
                         cudaFuncAttributeMaxDynamicSharedMemorySize,
                         SMEM_ATTN_BYTES);
    flash_attn_kernel<<<dim3(S_LEN / AQ, B_SZ * NH), 256, SMEM_ATTN_BYTES>>>();

    split_bf16_kernel<<<(xn4 + 255) / 256, 256>>>(o, ohi, olo, xn4);
    gemm_mma_bf16x3<<<gg, 256, GEMM_SMEM>>>(ohi, olo, wohi, wolo, out);
}

// round 7
// speedup vs baseline: 2.8084x; 1.7954x over previous
#include <cuda_runtime.h>
#include <cuda_bf16.h>
#include <stdint.h>
#include <math.h>

#define S_LEN 2048
#define B_SZ 2
#define D_MODEL 2048
#define NH 16
#define HD 128
#define MROWS (B_SZ * S_LEN)
#define KDIM 2048

// ---------------- scratch (static device allocations: allowed) ----------------
__device__ float g_q[(size_t)B_SZ * S_LEN * D_MODEL];
__device__ float g_k[(size_t)B_SZ * S_LEN * D_MODEL];
__device__ float g_v[(size_t)B_SZ * S_LEN * D_MODEL];
__device__ float g_o[(size_t)B_SZ * S_LEN * D_MODEL];
__device__ float g_cos[S_LEN * (HD / 2)];
__device__ float g_sin[S_LEN * (HD / 2)];

__device__ __nv_bfloat16 g_xhi[(size_t)MROWS * D_MODEL];
__device__ __nv_bfloat16 g_xlo[(size_t)MROWS * D_MODEL];
__device__ __nv_bfloat16 g_ohi[(size_t)MROWS * D_MODEL];
__device__ __nv_bfloat16 g_olo[(size_t)MROWS * D_MODEL];
__device__ __nv_bfloat16 g_wqhi[(size_t)D_MODEL * D_MODEL];
__device__ __nv_bfloat16 g_wqlo[(size_t)D_MODEL * D_MODEL];
__device__ __nv_bfloat16 g_wkhi[(size_t)D_MODEL * D_MODEL];
__device__ __nv_bfloat16 g_wklo[(size_t)D_MODEL * D_MODEL];
__device__ __nv_bfloat16 g_wvhi[(size_t)D_MODEL * D_MODEL];
__device__ __nv_bfloat16 g_wvlo[(size_t)D_MODEL * D_MODEL];
__device__ __nv_bfloat16 g_wohi[(size_t)D_MODEL * D_MODEL];
__device__ __nv_bfloat16 g_wolo[(size_t)D_MODEL * D_MODEL];

// bf16 hi/lo splits of roped q, roped k, and v (for tensor-core attention)
__device__ __nv_bfloat16 g_qh[(size_t)MROWS * D_MODEL];
__device__ __nv_bfloat16 g_ql[(size_t)MROWS * D_MODEL];
__device__ __nv_bfloat16 g_kh[(size_t)MROWS * D_MODEL];
__device__ __nv_bfloat16 g_kl[(size_t)MROWS * D_MODEL];
__device__ __nv_bfloat16 g_vh[(size_t)MROWS * D_MODEL];
__device__ __nv_bfloat16 g_vl[(size_t)MROWS * D_MODEL];

// ======================= low-level helpers ====================================
__device__ __forceinline__ uint32_t smem_u32(const void* p) {
    uint32_t a;
    asm("{ .reg .u64 t; cvta.to.shared.u64 t, %1; cvt.u32.u64 %0, t; }" : "=r"(a) : "l"(p));
    return a;
}
__device__ __forceinline__ void cp16(uint32_t dst, const void* src) {
    asm volatile("cp.async.cg.shared.global [%0], [%1], 16;" :: "r"(dst), "l"(src));
}
__device__ __forceinline__ void cp_commit() {
    asm volatile("cp.async.commit_group;" ::: "memory");
}
#define CP_WAIT(n) asm volatile("cp.async.wait_group " #n ";" ::: "memory")

__device__ __forceinline__ void ldsm_x4(uint32_t* r, uint32_t addr) {
    asm volatile("ldmatrix.sync.aligned.m8n8.x4.shared.b16 {%0,%1,%2,%3}, [%4];"
                 : "=r"(r[0]), "=r"(r[1]), "=r"(r[2]), "=r"(r[3]) : "r"(addr));
}
__device__ __forceinline__ void ldsm_x4_t(uint32_t* r, uint32_t addr) {
    asm volatile("ldmatrix.sync.aligned.m8n8.x4.trans.shared.b16 {%0,%1,%2,%3}, [%4];"
                 : "=r"(r[0]), "=r"(r[1]), "=r"(r[2]), "=r"(r[3]) : "r"(addr));
}
__device__ __forceinline__ void mma_bf16(float* d, const uint32_t* a, const uint32_t* b) {
    asm volatile(
        "mma.sync.aligned.m16n8k16.row.col.f32.bf16.bf16.f32 "
        "{%0,%1,%2,%3}, {%4,%5,%6,%7}, {%8,%9}, {%0,%1,%2,%3};"
        : "+f"(d[0]), "+f"(d[1]), "+f"(d[2]), "+f"(d[3])
        : "r"(a[0]), "r"(a[1]), "r"(a[2]), "r"(a[3]), "r"(b[0]), "r"(b[1]));
}

// swizzles: 128B rows (GEMM) and 256B rows (attention)
#define SWZ(x) ((x) ^ (((x) >> 3) & 0x70))
#define SWZ256(x) ((x) ^ (((x) >> 4) & 0x70))

// ======================= bf16x3 tensor-core GEMM (mma.sync) ==================
#define GBM 128
#define GBN 128
#define NCHUNK (KDIM / 64)
#define TILE_B (GBM * 128)
#define STAGE_B (4 * TILE_B)
#define GEMM_SMEM (2 * STAGE_B)

__device__ __forceinline__ void gemm_issue(
    const __nv_bfloat16* Ah, const __nv_bfloat16* Al,
    const __nv_bfloat16* Bh, const __nv_bfloat16* Bl,
    uint32_t sb0, int m0, int n0, int tid, int c, int s)
{
    const uint32_t st = sb0 + (uint32_t)s * STAGE_B;
    const size_t kb = (size_t)c * 128;
    const int lq = tid & 7;
#pragma unroll
    for (int i = 0; i < 4; i++) {
        const int r = (tid + i * 256) >> 3;
        const uint32_t dsw = SWZ((uint32_t)(r * 128 + lq * 16));
        const size_t arow = (size_t)(m0 + r) * (KDIM * 2) + kb + (size_t)lq * 16;
        const size_t brow = (size_t)(n0 + r) * (KDIM * 2) + kb + (size_t)lq * 16;
        cp16(st + dsw,              (const char*)Ah + arow);
        cp16(st + TILE_B + dsw,     (const char*)Al + arow);
        cp16(st + 2 * TILE_B + dsw, (const char*)Bh + brow);
        cp16(st + 3 * TILE_B + dsw, (const char*)Bl + brow);
    }
    cp_commit();
}

__global__ __launch_bounds__(256) void gemm_mma_bf16x3(
    const __nv_bfloat16* __restrict__ Ah, const __nv_bfloat16* __restrict__ Al,
    const __nv_bfloat16* __restrict__ Bh, const __nv_bfloat16* __restrict__ Bl,
    float* __restrict__ C)
{
    extern __shared__ char smem[];
    const uint32_t sb0 = smem_u32(smem);

    const int tid = threadIdx.x;
    const int wid = tid >> 5;
    const int lane = tid & 31;
    const int wm = wid >> 2;
    const int wn = wid & 3;
    const int m_base = wm * 64;
    const int n_base = wn * 32;
    const int m0 = blockIdx.y * GBM;
    const int n0 = blockIdx.x * GBN;

    float acc[4][4][4];
#pragma unroll
    for (int i = 0; i < 4; i++) {
#pragma unroll
        for (int j = 0; j < 4; j++) {
#pragma unroll
            for (int e = 0; e < 4; e++) { acc[i][j][e] = 0.f; }
        }
    }

    gemm_issue(Ah, Al, Bh, Bl, sb0, m0, n0, tid, 0, 0);
    gemm_issue(Ah, Al, Bh, Bl, sb0, m0, n0, tid, 1, 1);

    const int g8 = lane >> 3;
    const int r8 = lane & 7;
    const int rowoff = (g8 & 1) * 8 + r8;
    const int qhi = g8 >> 1;

    for (int c = 0; c < NCHUNK; c++) {
        const int s = c & 1;
        CP_WAIT(1);
        __syncthreads();
        const uint32_t sAh = sb0 + (uint32_t)s * STAGE_B;
        const uint32_t sAl = sAh + TILE_B;
        const uint32_t sBh = sAh + 2 * TILE_B;
        const uint32_t sBl = sAh + 3 * TILE_B;

#pragma unroll
        for (int ks = 0; ks < 4; ks++) {
            const int quad = ks * 2 + qhi;
            uint32_t ah[4][4], al[4][4], bh[4][2], bl[4][2];
#pragma unroll
            for (int mi = 0; mi < 4; mi++) {
                const uint32_t off = SWZ((uint32_t)((m_base + mi * 16 + rowoff) * 128 + quad * 16));
                ldsm_x4(ah[mi], sAh + off);
                ldsm_x4(al[mi], sAl + off);
            }
#pragma unroll
            for (int p = 0; p < 2; p++) {
                const uint32_t off = SWZ((uint32_t)((n_base + p * 16 + rowoff) * 128 + quad * 16));
                uint32_t t[4];
                ldsm_x4(t, sBh + off);
                bh[2 * p][0] = t[0]; bh[2 * p][1] = t[2];
                bh[2 * p + 1][0] = t[1]; bh[2 * p + 1][1] = t[3];
                ldsm_x4(t, sBl + off);
                bl[2 * p][0] = t[0]; bl[2 * p][1] = t[2];
                bl[2 * p + 1][0] = t[1]; bl[2 * p + 1][1] = t[3];
            }
#pragma unroll
            for (int mi = 0; mi < 4; mi++) {
#pragma unroll
                for (int ni = 0; ni < 4; ni++) {
                    mma_bf16(acc[mi][ni], ah[mi], bh[ni]);
                    mma_bf16(acc[mi][ni], ah[mi], bl[ni]);
                    mma_bf16(acc[mi][ni], al[mi], bh[ni]);
                }
            }
        }
        __syncthreads();
        if (c + 2 < NCHUNK) {
            gemm_issue(Ah, Al, Bh, Bl, sb0, m0, n0, tid, c + 2, s);
        }
    }

    const int erow = lane >> 2;
    const int ecol = (lane & 3) * 2;
#pragma unroll
    for (int mi = 0; mi < 4; mi++) {
#pragma unroll
        for (int ni = 0; ni < 4; ni++) {
            const int row = m0 + m_base + mi * 16 + erow;
            const int col = n0 + n_base + ni * 8 + ecol;
            *(float2*)(C + (size_t)row * D_MODEL + col) =
                make_float2(acc[mi][ni][0], acc[mi][ni][1]);
            *(float2*)(C + (size_t)(row + 8) * D_MODEL + col) =
                make_float2(acc[mi][ni][2], acc[mi][ni][3]);
        }
    }
}

// ---------------- fp32 -> (hi, lo) bf16 split ----------------
__global__ void split_bf16_kernel(const float* __restrict__ src,
                                  __nv_bfloat16* __restrict__ hi,
                                  __nv_bfloat16* __restrict__ lo, int n4)
{
    int i = blockIdx.x * blockDim.x + threadIdx.x;
    if (i >= n4) return;
    float4 f = ((const float4*)src)[i];
    __nv_bfloat16 h0 = __float2bfloat16(f.x);
    __nv_bfloat16 h1 = __float2bfloat16(f.y);
    __nv_bfloat16 h2 = __float2bfloat16(f.z);
    __nv_bfloat16 h3 = __float2bfloat16(f.w);
    __nv_bfloat16 l0 = __float2bfloat16(f.x - __bfloat162float(h0));
    __nv_bfloat16 l1 = __float2bfloat16(f.y - __bfloat162float(h1));
    __nv_bfloat16 l2 = __float2bfloat16(f.z - __bfloat162float(h2));
    __nv_bfloat16 l3 = __float2bfloat16(f.w - __bfloat162float(h3));
    ushort4 hv, lv;
    hv.x = __bfloat16_as_ushort(h0); hv.y = __bfloat16_as_ushort(h1);
    hv.z = __bfloat16_as_ushort(h2); hv.w = __bfloat16_as_ushort(h3);
    lv.x = __bfloat16_as_ushort(l0); lv.y = __bfloat16_as_ushort(l1);
    lv.z = __bfloat16_as_ushort(l2); lv.w = __bfloat16_as_ushort(l3);
    ((ushort4*)hi)[i] = hv;
    ((ushort4*)lo)[i] = lv;
}

// ---------------- RoPE table (double precision angles) ----------------
__global__ void rope_table_kernel() {
    int idx = blockIdx.x * blockDim.x + threadIdx.x;
    if (idx >= S_LEN * (HD / 2)) return;
    int s = idx >> 6;
    int i = idx & 63;
    double freq = exp(-log(10000.0) * (double)(2 * i) / (double)HD);
    double ang = (double)s * freq;
    g_cos[idx] = (float)cos(ang);
    g_sin[idx] = (float)sin(ang);
}

// ---------------- RoPE apply + fp32->bf16 hi/lo split (q or k) ----------------
__global__ void rope_split_kernel(const float* __restrict__ t,
                                  __nv_bfloat16* __restrict__ hi,
                                  __nv_bfloat16* __restrict__ lo)
{
    const int NP = B_SZ * S_LEN * D_MODEL / 2;
    int idx = blockIdx.x * blockDim.x + threadIdx.x;
    if (idx >= NP) return;
    int d2 = idx & (D_MODEL / 2 - 1);
    int s  = (idx / (D_MODEL / 2)) & (S_LEN - 1);
    int i  = d2 & 63;
    float c  = g_cos[(s << 6) + i];
    float sn = g_sin[(s << 6) + i];
    float2 v = *(const float2*)(t + 2 * (size_t)idx);
    float r0 = v.x * c - v.y * sn;
    float r1 = v.x * sn + v.y * c;
    __nv_bfloat16 h0 = __float2bfloat16(r0);
    __nv_bfloat16 h1 = __float2bfloat16(r1);
    __nv_bfloat16 e0 = __float2bfloat16(r0 - __bfloat162float(h0));
    __nv_bfloat16 e1 = __float2bfloat16(r1 - __bfloat162float(h1));
    ushort2 hv, lv;
    hv.x = __bfloat16_as_ushort(h0); hv.y = __bfloat16_as_ushort(h1);
    lv.x = __bfloat16_as_ushort(e0); lv.y = __bfloat16_as_ushort(e1);
    ((ushort2*)hi)[idx] = hv;
    ((ushort2*)lo)[idx] = lv;
}

// ============== Flash attention (causal) with bf16x3 mma.sync ================
// AQ=64 q-rows/CTA (4 warps x 16), AK=32 k-cols/iter, hd=128.
// smem: Qhi 16K | Qlo 16K | 2 stages x {Khi 8K, Klo 8K, Vhi 8K, Vlo 8K}
#define FAQ 64
#define FAK 32
#define FA_QHI 0
#define FA_QLO 16384
#define FA_STG 32768
#define FA_TILE 8192
#define FA_STAGE (4 * FA_TILE)
#define FA_SMEM (FA_STG + 2 * FA_STAGE)   // 98304

__device__ __forceinline__ void fa_issue_stage(
    uint32_t sb, int s, int k0, int tid,
    const __nv_bfloat16* kh, const __nv_bfloat16* kl,
    const __nv_bfloat16* vh, const __nv_bfloat16* vl)
{
    const uint32_t st = sb + FA_STG + (uint32_t)s * FA_STAGE;
    const __nv_bfloat16* gp[4];
    gp[0] = kh; gp[1] = kl; gp[2] = vh; gp[3] = vl;
#pragma unroll
    for (int t = 0; t < 4; t++) {
#pragma unroll
        for (int i = 0; i < 4; i++) {
            int idx = i * 128 + tid;
            int row = idx >> 4, ch = idx & 15;
            uint32_t dst = st + (uint32_t)t * FA_TILE
                         + SWZ256((uint32_t)(row * 256 + ch * 16));
            const char* src = (const char*)gp[t]
                            + (size_t)(k0 + row) * (D_MODEL * 2) + (size_t)ch * 16;
            cp16(dst, src);
        }
    }
    cp_commit();
}

__global__ __launch_bounds__(128, 2) void flash_attn_mma() {
    extern __shared__ char smraw[];
    const uint32_t sb = smem_u32(smraw);
    const int tid = threadIdx.x;
    const int lane = tid & 31;
    const int w = tid >> 5;
    const int qt = (int)gridDim.x - 1 - (int)blockIdx.x;   // heavy tiles first
    const int bh = blockIdx.y;
    const int b = bh >> 4, h = bh & 15;
    const int q0 = qt * FAQ;
    const int n_kt = 2 * qt + 2;

    const size_t base = (size_t)b * S_LEN * D_MODEL + (size_t)h * HD;
    const __nv_bfloat16* qh = g_qh + base;
    const __nv_bfloat16* ql = g_ql + base;
    const __nv_bfloat16* kh = g_kh + base;
    const __nv_bfloat16* kl = g_kl + base;
    const __nv_bfloat16* vh = g_vh + base;
    const __nv_bfloat16* vl = g_vl + base;
    float* op = g_o + base;

    // --- Q load (group 0): 64 rows x 16 chunks, hi + lo
#pragma unroll
    for (int i = 0; i < 8; i++) {
        int idx = i * 128 + tid;
        int row = idx >> 4, ch = idx & 15;
        uint32_t dsw = SWZ256((uint32_t)(row * 256 + ch * 16));
        const char* srch = (const char*)qh + (size_t)(q0 + row) * (D_MODEL * 2) + (size_t)ch * 16;
        const char* srcl = (const char*)ql + (size_t)(q0 + row) * (D_MODEL * 2) + (size_t)ch * 16;
        cp16(sb + FA_QHI + dsw, srch);
        cp16(sb + FA_QLO + dsw, srcl);
    }
    cp_commit();
    fa_issue_stage(sb, 0, 0, tid, kh, kl, vh, vl);
    fa_issue_stage(sb, 1, FAK, tid, kh, kl, vh, vl);

    const int g8 = lane >> 3;
    const int r8 = lane & 7;
    const int rowoff = (g8 & 1) * 8 + r8;
    const int qsel = g8 >> 1;

    float oacc[16][4];
#pragma unroll
    for (int t = 0; t < 16; t++) {
#pragma unroll
        for (int e = 0; e < 4; e++) { oacc[t][e] = 0.f; }
    }
    float m0 = -1e30f, m1 = -1e30f, l0 = 0.f, l1 = 0.f;
    const float sm_scale = 0.08838834764831843f;

    const int lrow0 = q0 + w * 16 + (lane >> 2);   // global q row of regs 0,1
    const int lcolb = (lane & 3) * 2;

    for (int kt = 0; kt < n_kt; kt++) {
        const int s = kt & 1;
        const int k0 = kt * FAK;
        CP_WAIT(1);
        __syncthreads();
        const uint32_t stg = sb + FA_STG + (uint32_t)s * FA_STAGE;

        // ---- scores S[16][32] = Q @ K^T (bf16x3) ----
        float sacc[4][4];
#pragma unroll
        for (int t = 0; t < 4; t++) {
#pragma unroll
            for (int e = 0; e < 4; e++) { sacc[t][e] = 0.f; }
        }
#pragma unroll
        for (int ks = 0; ks < 8; ks++) {
            const int quad = ks * 2 + qsel;
            uint32_t qfh[4], qfl[4];
            const uint32_t qoff = SWZ256((uint32_t)((w * 16 + rowoff) * 256 + quad * 16));
            ldsm_x4(qfh, sb + FA_QHI + qoff);
            ldsm_x4(qfl, sb + FA_QLO + qoff);
#pragma unroll
            for (int nt = 0; nt < 2; nt++) {
                const uint32_t koff = SWZ256((uint32_t)((nt * 16 + rowoff) * 256 + quad * 16));
                uint32_t tkh[4], tkl[4];
                ldsm_x4(tkh, stg + koff);                 // Khi tile
                ldsm_x4(tkl, stg + FA_TILE + koff);       // Klo tile
                uint32_t bh0[2], bh1[2], bl0[2], bl1[2];
                bh0[0] = tkh[0]; bh0[1] = tkh[2];
                bh1[0] = tkh[1]; bh1[1] = tkh[3];
                bl0[0] = tkl[0]; bl0[1] = tkl[2];
                bl1[0] = tkl[1]; bl1[1] = tkl[3];
                mma_bf16(sacc[nt * 2],     qfh, bh0);
                mma_bf16(sacc[nt * 2],     qfh, bl0);
                mma_bf16(sacc[nt * 2],     qfl, bh0);
                mma_bf16(sacc[nt * 2 + 1], qfh, bh1);
                mma_bf16(sacc[nt * 2 + 1], qfh, bl1);
                mma_bf16(sacc[nt * 2 + 1], qfl, bh1);
            }
        }

        // ---- scale + causal mask ----
        const int need_mask = (k0 + FAK - 1 > q0 + w * 16) ? 1 : 0;
#pragma unroll
        for (int t = 0; t < 4; t++) {
#pragma unroll
            for (int e = 0; e < 4; e++) {
                float sv = sacc[t][e] * sm_scale;
                if (need_mask) {
                    int col = k0 + t * 8 + lcolb + (e & 1);
                    int row = lrow0 + ((e >> 1) & 1) * 8;
                    if (col > row) { sv = -1e30f; }
                }
                sacc[t][e] = sv;
            }
        }

        // ---- online softmax (rows spread over 4-lane groups) ----
        float rm0 = sacc[0][0], rm1 = sacc[0][2];
#pragma unroll
        for (int t = 0; t < 4; t++) {
            rm0 = fmaxf(rm0, fmaxf(sacc[t][0], sacc[t][1]));
            rm1 = fmaxf(rm1, fmaxf(sacc[t][2], sacc[t][3]));
        }
        rm0 = fmaxf(rm0, __shfl_xor_sync(0xffffffffu, rm0, 1));
        rm0 = fmaxf(rm0, __shfl_xor_sync(0xffffffffu, rm0, 2));
        rm1 = fmaxf(rm1, __shfl_xor_sync(0xffffffffu, rm1, 1));
        rm1 = fmaxf(rm1, __shfl_xor_sync(0xffffffffu, rm1, 2));
        float mn0 = fmaxf(m0, rm0);
        float mn1 = fmaxf(m1, rm1);
        float alpha0 = expf(m0 - mn0);
        float alpha1 = expf(m1 - mn1);
        float rs0 = 0.f, rs1 = 0.f;
#pragma unroll
        for (int t = 0; t < 4; t++) {
            float p0 = expf(sacc[t][0] - mn0);
            float p1 = expf(sacc[t][1] - mn0);
            float p2 = expf(sacc[t][2] - mn1);
            float p3 = expf(sacc[t][3] - mn1);
            rs0 += p0 + p1;
            rs1 += p2 + p3;
            sacc[t][0] = p0; sacc[t][1] = p1;
            sacc[t][2] = p2; sacc[t][3] = p3;
        }
        rs0 += __shfl_xor_sync(0xffffffffu, rs0, 1);
        rs0 += __shfl_xor_sync(0xffffffffu, rs0, 2);
        rs1 += __shfl_xor_sync(0xffffffffu, rs1, 1);
        rs1 += __shfl_xor_sync(0xffffffffu, rs1, 2);
        l0 = l0 * alpha0 + rs0;
        l1 = l1 * alpha1 + rs1;
        m0 = mn0; m1 = mn1;
#pragma unroll
        for (int t = 0; t < 16; t++) {
            oacc[t][0] *= alpha0; oacc[t][1] *= alpha0;
            oacc[t][2] *= alpha1; oacc[t][3] *= alpha1;
        }

        // ---- pack P into bf16 hi/lo A-frags (C-frag -> A-frag identity) ----
        uint32_t pfh[2][4], pfl[2][4];
#pragma unroll
        for (int j = 0; j < 2; j++) {
#pragma unroll
            for (int idx = 0; idx < 4; idx++) {
                int st = 2 * j + (idx >> 1);
                int rp = (idx & 1) * 2;
                float f0 = sacc[st][rp];
                float f1 = sacc[st][rp + 1];
                __nv_bfloat16 h0 = __float2bfloat16(f0);
                __nv_bfloat16 h1 = __float2bfloat16(f1);
                float r0f = f0 - __bfloat162float(h0);
                float r1f = f1 - __bfloat162float(h1);
                __nv_bfloat16 e0 = __float2bfloat16(r0f);
                __nv_bfloat16 e1 = __float2bfloat16(r1f);
                pfh[j][idx] = (uint32_t)__bfloat16_as_ushort(h0)
                            | ((uint32_t)__bfloat16_as_ushort(h1) << 16);
                pfl[j][idx] = (uint32_t)__bfloat16_as_ushort(e0)
                            | ((uint32_t)__bfloat16_as_ushort(e1) << 16);
            }
        }

        // ---- O += P @ V (bf16x3), V loaded via trans ldmatrix ----
        const int vrow_base = (lane & 7) + ((lane >> 3) & 1) * 8;
        const int vcol_base = ((lane >> 4) & 1) * 16;
#pragma unroll
        for (int j = 0; j < 2; j++) {
#pragma unroll
            for (int nt = 0; nt < 8; nt++) {
                const int vr = j * 16 + vrow_base;
                const int vcb = nt * 32 + vcol_base;
                const uint32_t voff = SWZ256((uint32_t)(vr * 256 + vcb));
                uint32_t tvh[4], tvl[4];
                ldsm_x4_t(tvh, stg + 2 * FA_TILE + voff);
                ldsm_x4_t(tvl, stg + 3 * FA_TILE + voff);
                uint32_t bh0[2], bh1[2], bl0[2], bl1[2];
                bh0[0] = tvh[0]; bh0[1] = tvh[1];
                bh1[0] = tvh[2]; bh1[1] = tvh[3];
                bl0[0] = tvl[0]; bl0[1] = tvl[1];
                bl1[0] = tvl[2]; bl1[1] = tvl[3];
                mma_bf16(oacc[nt * 2],     pfh[j], bh0);
                mma_bf16(oacc[nt * 2],     pfh[j], bl0);
                mma_bf16(oacc[nt * 2],     pfl[j], bh0);
                mma_bf16(oacc[nt * 2 + 1], pfh[j], bh1);
                mma_bf16(oacc[nt * 2 + 1], pfh[j], bl1);
                mma_bf16(oacc[nt * 2 + 1], pfl[j], bh1);
            }
        }

        __syncthreads();
        if (kt + 2 < n_kt) {
            fa_issue_stage(sb, s, (kt + 2) * FAK, tid, kh, kl, vh, vl);
        } else {
            cp_commit();   // keep group accounting uniform
        }
    }

    // ---- epilogue: normalize, store fp32 ----
    const float inv0 = 1.f / l0;
    const float inv1 = 1.f / l1;
#pragma unroll
    for (int t = 0; t < 16; t++) {
        const int col = t * 8 + lcolb;
        *(float2*)(op + (size_t)lrow0 * D_MODEL + col) =
            make_float2(oacc[t][0] * inv0, oacc[t][1] * inv0);
        *(float2*)(op + (size_t)(lrow0 + 8) * D_MODEL + col) =
            make_float2(oacc[t][2] * inv1, oacc[t][3] * inv1);
    }
}

// ======================= host side =======================
extern "C" void kernel_launch(void* const* d_in, const int* in_sizes, int n_in,
                              void* d_out, int out_size) {
    const float* x  = (const float*)d_in[0];
    const float* wq = (const float*)d_in[1];
    const float* wk = (const float*)d_in[2];
    const float* wv = (const float*)d_in[3];
    const float* wo = (const float*)d_in[4];
    float* out = (float*)d_out;

    float *q, *k, *v, *o;
    cudaGetSymbolAddress((void**)&q, g_q);
    cudaGetSymbolAddress((void**)&k, g_k);
    cudaGetSymbolAddress((void**)&v, g_v);
    cudaGetSymbolAddress((void**)&o, g_o);

    __nv_bfloat16 *xhi, *xlo, *ohi, *olo;
    __nv_bfloat16 *wqhi, *wqlo, *wkhi, *wklo, *wvhi, *wvlo, *wohi, *wolo;
    __nv_bfloat16 *qh, *ql, *kh, *kl, *vh, *vl;
    cudaGetSymbolAddress((void**)&xhi, g_xhi);  cudaGetSymbolAddress((void**)&xlo, g_xlo);
    cudaGetSymbolAddress((void**)&ohi, g_ohi);  cudaGetSymbolAddress((void**)&olo, g_olo);
    cudaGetSymbolAddress((void**)&wqhi, g_wqhi); cudaGetSymbolAddress((void**)&wqlo, g_wqlo);
    cudaGetSymbolAddress((void**)&wkhi, g_wkhi); cudaGetSymbolAddress((void**)&wklo, g_wklo);
    cudaGetSymbolAddress((void**)&wvhi, g_wvhi); cudaGetSymbolAddress((void**)&wvlo, g_wvlo);
    cudaGetSymbolAddress((void**)&wohi, g_wohi); cudaGetSymbolAddress((void**)&wolo, g_wolo);
    cudaGetSymbolAddress((void**)&qh, g_qh); cudaGetSymbolAddress((void**)&ql, g_ql);
    cudaGetSymbolAddress((void**)&kh, g_kh); cudaGetSymbolAddress((void**)&kl, g_kl);
    cudaGetSymbolAddress((void**)&vh, g_vh); cudaGetSymbolAddress((void**)&vl, g_vl);

    rope_table_kernel<<<(S_LEN * (HD / 2) + 255) / 256, 256>>>();

    const int xn4 = MROWS * D_MODEL / 4;
    const int wn4 = D_MODEL * D_MODEL / 4;
    split_bf16_kernel<<<(xn4 + 255) / 256, 256>>>(x, xhi, xlo, xn4);
    split_bf16_kernel<<<(wn4 + 255) / 256, 256>>>(wq, wqhi, wqlo, wn4);
    split_bf16_kernel<<<(wn4 + 255) / 256, 256>>>(wk, wkhi, wklo, wn4);
    split_bf16_kernel<<<(wn4 + 255) / 256, 256>>>(wv, wvhi, wvlo, wn4);
    split_bf16_kernel<<<(wn4 + 255) / 256, 256>>>(wo, wohi, wolo, wn4);

    cudaFuncSetAttribute(gemm_mma_bf16x3, cudaFuncAttributeMaxDynamicSharedMemorySize, GEMM_SMEM);
    dim3 gg(D_MODEL / GBN, MROWS / GBM);
    gemm_mma_bf16x3<<<gg, 256, GEMM_SMEM>>>(xhi, xlo, wqhi, wqlo, q);
    gemm_mma_bf16x3<<<gg, 256, GEMM_SMEM>>>(xhi, xlo, wkhi, wklo, k);
    gemm_mma_bf16x3<<<gg, 256, GEMM_SMEM>>>(xhi, xlo, wvhi, wvlo, v);

    const int np = B_SZ * S_LEN * D_MODEL / 2;
    rope_split_kernel<<<(np + 255) / 256, 256>>>(q, qh, ql);
    rope_split_kernel<<<(np + 255) / 256, 256>>>(k, kh, kl);
    split_bf16_kernel<<<(xn4 + 255) / 256, 256>>>(v, vh, vl, xn4);

    cudaFuncSetAttribute(flash_attn_mma, cudaFuncAttributeMaxDynamicSharedMemorySize, FA_SMEM);
    flash_attn_mma<<<dim3(S_LEN / FAQ, B_SZ * NH), 128, FA_SMEM>>>();

    split_bf16_kernel<<<(xn4 + 255) / 256, 256>>>(o, ohi, olo, xn4);
    gemm_mma_bf16x3<<<gg, 256, GEMM_SMEM>>>(ohi, olo, wohi, wolo, out);
}

// round 8
// speedup vs baseline: 4.2628x; 1.5179x over previous
#include <cuda_runtime.h>
#include <cuda_bf16.h>
#include <cuda_fp16.h>
#include <stdint.h>
#include <math.h>

#define S_LEN 2048
#define B_SZ 2
#define D_MODEL 2048
#define NH 16
#define HD 128
#define MROWS (B_SZ * S_LEN)
#define KDIM 2048

// ---------------- scratch (static device allocations: allowed) ----------------
__device__ float g_q[(size_t)B_SZ * S_LEN * D_MODEL];
__device__ float g_k[(size_t)B_SZ * S_LEN * D_MODEL];
__device__ float g_v[(size_t)B_SZ * S_LEN * D_MODEL];
__device__ float g_o[(size_t)B_SZ * S_LEN * D_MODEL];
__device__ float g_cos[S_LEN * (HD / 2)];
__device__ float g_sin[S_LEN * (HD / 2)];

// fp16 split activations + fp16 weights (2-pass GEMM path)
__device__ __half g_xh2[(size_t)MROWS * D_MODEL];
__device__ __half g_xl2[(size_t)MROWS * D_MODEL];
__device__ __half g_oh2[(size_t)MROWS * D_MODEL];
__device__ __half g_ol2[(size_t)MROWS * D_MODEL];
__device__ __half g_wq16[(size_t)D_MODEL * D_MODEL];
__device__ __half g_wk16[(size_t)D_MODEL * D_MODEL];
__device__ __half g_wv16[(size_t)D_MODEL * D_MODEL];
__device__ __half g_wo16[(size_t)D_MODEL * D_MODEL];

// bf16 hi/lo splits of roped q, roped k, and v (bf16x3 attention)
__device__ __nv_bfloat16 g_qh[(size_t)MROWS * D_MODEL];
__device__ __nv_bfloat16 g_ql[(size_t)MROWS * D_MODEL];
__device__ __nv_bfloat16 g_kh[(size_t)MROWS * D_MODEL];
__device__ __nv_bfloat16 g_kl[(size_t)MROWS * D_MODEL];
__device__ __nv_bfloat16 g_vh[(size_t)MROWS * D_MODEL];
__device__ __nv_bfloat16 g_vl[(size_t)MROWS * D_MODEL];

// ======================= low-level helpers ====================================
__device__ __forceinline__ uint32_t smem_u32(const void* p) {
    uint32_t a;
    asm("{ .reg .u64 t; cvta.to.shared.u64 t, %1; cvt.u32.u64 %0, t; }" : "=r"(a) : "l"(p));
    return a;
}
__device__ __forceinline__ void cp16(uint32_t dst, const void* src) {
    asm volatile("cp.async.cg.shared.global [%0], [%1], 16;" :: "r"(dst), "l"(src));
}
__device__ __forceinline__ void cp_commit() {
    asm volatile("cp.async.commit_group;" ::: "memory");
}
#define CP_WAIT(n) asm volatile("cp.async.wait_group " #n ";" ::: "memory")

__device__ __forceinline__ void ldsm_x4(uint32_t* r, uint32_t addr) {
    asm volatile("ldmatrix.sync.aligned.m8n8.x4.shared.b16 {%0,%1,%2,%3}, [%4];"
                 : "=r"(r[0]), "=r"(r[1]), "=r"(r[2]), "=r"(r[3]) : "r"(addr));
}
__device__ __forceinline__ void ldsm_x4_t(uint32_t* r, uint32_t addr) {
    asm volatile("ldmatrix.sync.aligned.m8n8.x4.trans.shared.b16 {%0,%1,%2,%3}, [%4];"
                 : "=r"(r[0]), "=r"(r[1]), "=r"(r[2]), "=r"(r[3]) : "r"(addr));
}
__device__ __forceinline__ void mma_bf16(float* d, const uint32_t* a, const uint32_t* b) {
    asm volatile(
        "mma.sync.aligned.m16n8k16.row.col.f32.bf16.bf16.f32 "
        "{%0,%1,%2,%3}, {%4,%5,%6,%7}, {%8,%9}, {%0,%1,%2,%3};"
        : "+f"(d[0]), "+f"(d[1]), "+f"(d[2]), "+f"(d[3])
        : "r"(a[0]), "r"(a[1]), "r"(a[2]), "r"(a[3]), "r"(b[0]), "r"(b[1]));
}
__device__ __forceinline__ void mma_f16(float* d, const uint32_t* a, const uint32_t* b) {
    asm volatile(
        "mma.sync.aligned.m16n8k16.row.col.f32.f16.f16.f32 "
        "{%0,%1,%2,%3}, {%4,%5,%6,%7}, {%8,%9}, {%0,%1,%2,%3};"
        : "+f"(d[0]), "+f"(d[1]), "+f"(d[2]), "+f"(d[3])
        : "r"(a[0]), "r"(a[1]), "r"(a[2]), "r"(a[3]), "r"(b[0]), "r"(b[1]));
}

// swizzles: 128B rows (GEMM) and 256B rows (attention)
#define SWZ(x) ((x) ^ (((x) >> 3) & 0x70))
#define SWZ256(x) ((x) ^ (((x) >> 4) & 0x70))

// =========== fp16x2 2-pass GEMM: C = (Ah+Al) @ Bf16^T, triple-output ==========
#define GBM 128
#define GBN 128
#define NCHUNK (KDIM / 64)
#define TILE_B (GBM * 128)
#define STAGE_B (3 * TILE_B)      // Ah, Al, Bh tiles
#define GEMM_SMEM (2 * STAGE_B)   // 98304

__device__ __forceinline__ void gemm_issue2(
    const __half* Ah, const __half* Al, const __half* Bh,
    uint32_t sb0, int m0, int n0, int tid, int c, int s)
{
    const uint32_t st = sb0 + (uint32_t)s * STAGE_B;
    const size_t kb = (size_t)c * 128;
    const int lq = tid & 7;
#pragma unroll
    for (int i = 0; i < 4; i++) {
        const int r = (tid + i * 256) >> 3;
        const uint32_t dsw = SWZ((uint32_t)(r * 128 + lq * 16));
        const size_t arow = (size_t)(m0 + r) * (KDIM * 2) + kb + (size_t)lq * 16;
        const size_t brow = (size_t)(n0 + r) * (KDIM * 2) + kb + (size_t)lq * 16;
        cp16(st + dsw,              (const char*)Ah + arow);
        cp16(st + TILE_B + dsw,     (const char*)Al + arow);
        cp16(st + 2 * TILE_B + dsw, (const char*)Bh + brow);
    }
    cp_commit();
}

__global__ __launch_bounds__(256) void gemm_f16x2_tri(
    const __half* __restrict__ Ah, const __half* __restrict__ Al,
    const __half* __restrict__ B0, const __half* __restrict__ B1,
    const __half* __restrict__ B2,
    float* __restrict__ C0, float* __restrict__ C1, float* __restrict__ C2)
{
    extern __shared__ char smem[];
    const uint32_t sb0 = smem_u32(smem);

    const int nb = blockIdx.x;
    const int which = nb >> 4;
    const int n0 = (nb & 15) * GBN;
    const __half* Bh = (which == 0) ? B0 : ((which == 1) ? B1 : B2);
    float* C = (which == 0) ? C0 : ((which == 1) ? C1 : C2);

    const int tid = threadIdx.x;
    const int wid = tid >> 5;
    const int lane = tid & 31;
    const int wm = wid >> 2;
    const int wn = wid & 3;
    const int m_base = wm * 64;
    const int n_base = wn * 32;
    const int m0 = blockIdx.y * GBM;

    float acc[4][4][4];
#pragma unroll
    for (int i = 0; i < 4; i++) {
#pragma unroll
        for (int j = 0; j < 4; j++) {
#pragma unroll
            for (int e = 0; e < 4; e++) { acc[i][j][e] = 0.f; }
        }
    }

    gemm_issue2(Ah, Al, Bh, sb0, m0, n0, tid, 0, 0);
    gemm_issue2(Ah, Al, Bh, sb0, m0, n0, tid, 1, 1);

    const int g8 = lane >> 3;
    const int r8 = lane & 7;
    const int rowoff = (g8 & 1) * 8 + r8;
    const int qhi = g8 >> 1;

    for (int c = 0; c < NCHUNK; c++) {
        const int s = c & 1;
        CP_WAIT(1);
        __syncthreads();
        const uint32_t sAh = sb0 + (uint32_t)s * STAGE_B;
        const uint32_t sAl = sAh + TILE_B;
        const uint32_t sBh = sAh + 2 * TILE_B;

#pragma unroll
        for (int ks = 0; ks < 4; ks++) {
            const int quad = ks * 2 + qhi;
            uint32_t ah[4][4], al[4][4], bh[4][2];
#pragma unroll
            for (int mi = 0; mi < 4; mi++) {
                const uint32_t off = SWZ((uint32_t)((m_base + mi * 16 + rowoff) * 128 + quad * 16));
                ldsm_x4(ah[mi], sAh + off);
                ldsm_x4(al[mi], sAl + off);
            }
#pragma unroll
            for (int p = 0; p < 2; p++) {
                const uint32_t off = SWZ((uint32_t)((n_base + p * 16 + rowoff) * 128 + quad * 16));
                uint32_t t[4];
                ldsm_x4(t, sBh + off);
                bh[2 * p][0] = t[0]; bh[2 * p][1] = t[2];
                bh[2 * p + 1][0] = t[1]; bh[2 * p + 1][1] = t[3];
            }
#pragma unroll
            for (int mi = 0; mi < 4; mi++) {
#pragma unroll
                for (int ni = 0; ni < 4; ni++) {
                    mma_f16(acc[mi][ni], ah[mi], bh[ni]);
                    mma_f16(acc[mi][ni], al[mi], bh[ni]);
                }
            }
        }
        __syncthreads();
        if (c + 2 < NCHUNK) {
            gemm_issue2(Ah, Al, Bh, sb0, m0, n0, tid, c + 2, s);
        }
    }

    const int erow = lane >> 2;
    const int ecol = (lane & 3) * 2;
#pragma unroll
    for (int mi = 0; mi < 4; mi++) {
#pragma unroll
        for (int ni = 0; ni < 4; ni++) {
            const int row = m0 + m_base + mi * 16 + erow;
            const int col = n0 + n_base + ni * 8 + ecol;
            *(float2*)(C + (size_t)row * D_MODEL + col) =
                make_float2(acc[mi][ni][0], acc[mi][ni][1]);
            *(float2*)(C + (size_t)(row + 8) * D_MODEL + col) =
                make_float2(acc[mi][ni][2], acc[mi][ni][3]);
        }
    }
}

// ---------------- fp32 -> (hi, lo) fp16 split ----------------
__global__ void split_f16_kernel(const float* __restrict__ src,
                                 __half* __restrict__ hi,
                                 __half* __restrict__ lo, int n4)
{
    int i = blockIdx.x * blockDim.x + threadIdx.x;
    if (i >= n4) return;
    float4 f = ((const float4*)src)[i];
    __half h0 = __float2half_rn(f.x);
    __half h1 = __float2half_rn(f.y);
    __half h2 = __float2half_rn(f.z);
    __half h3 = __float2half_rn(f.w);
    __half l0 = __float2half_rn(f.x - __half2float(h0));
    __half l1 = __float2half_rn(f.y - __half2float(h1));
    __half l2 = __float2half_rn(f.z - __half2float(h2));
    __half l3 = __float2half_rn(f.w - __half2float(h3));
    ushort4 hv, lv;
    hv.x = __half_as_ushort(h0); hv.y = __half_as_ushort(h1);
    hv.z = __half_as_ushort(h2); hv.w = __half_as_ushort(h3);
    lv.x = __half_as_ushort(l0); lv.y = __half_as_ushort(l1);
    lv.z = __half_as_ushort(l2); lv.w = __half_as_ushort(l3);
    ((ushort4*)hi)[i] = hv;
    ((ushort4*)lo)[i] = lv;
}

// ---------------- fp32 -> fp16 convert (weights) ----------------
__global__ void cvt_f16_kernel(const float* __restrict__ src,
                               __half* __restrict__ dst, int n4)
{
    int i = blockIdx.x * blockDim.x + threadIdx.x;
    if (i >= n4) return;
    float4 f = ((const float4*)src)[i];
    ushort4 hv;
    hv.x = __half_as_ushort(__float2half_rn(f.x));
    hv.y = __half_as_ushort(__float2half_rn(f.y));
    hv.z = __half_as_ushort(__float2half_rn(f.z));
    hv.w = __half_as_ushort(__float2half_rn(f.w));
    ((ushort4*)dst)[i] = hv;
}

// ---------------- fp32 -> (hi, lo) bf16 split (attention V) ----------------
__global__ void split_bf16_kernel(const float* __restrict__ src,
                                  __nv_bfloat16* __restrict__ hi,
                                  __nv_bfloat16* __restrict__ lo, int n4)
{
    int i = blockIdx.x * blockDim.x + threadIdx.x;
    if (i >= n4) return;
    float4 f = ((const float4*)src)[i];
    __nv_bfloat16 h0 = __float2bfloat16(f.x);
    __nv_bfloat16 h1 = __float2bfloat16(f.y);
    __nv_bfloat16 h2 = __float2bfloat16(f.z);
    __nv_bfloat16 h3 = __float2bfloat16(f.w);
    __nv_bfloat16 l0 = __float2bfloat16(f.x - __bfloat162float(h0));
    __nv_bfloat16 l1 = __float2bfloat16(f.y - __bfloat162float(h1));
    __nv_bfloat16 l2 = __float2bfloat16(f.z - __bfloat162float(h2));
    __nv_bfloat16 l3 = __float2bfloat16(f.w - __bfloat162float(h3));
    ushort4 hv, lv;
    hv.x = __bfloat16_as_ushort(h0); hv.y = __bfloat16_as_ushort(h1);
    hv.z = __bfloat16_as_ushort(h2); hv.w = __bfloat16_as_ushort(h3);
    lv.x = __bfloat16_as_ushort(l0); lv.y = __bfloat16_as_ushort(l1);
    lv.z = __bfloat16_as_ushort(l2); lv.w = __bfloat16_as_ushort(l3);
    ((ushort4*)hi)[i] = hv;
    ((ushort4*)lo)[i] = lv;
}

// ---------------- RoPE table (double precision angles) ----------------
__global__ void rope_table_kernel() {
    int idx = blockIdx.x * blockDim.x + threadIdx.x;
    if (idx >= S_LEN * (HD / 2)) return;
    int s = idx >> 6;
    int i = idx & 63;
    double freq = exp(-log(10000.0) * (double)(2 * i) / (double)HD);
    double ang = (double)s * freq;
    g_cos[idx] = (float)cos(ang);
    g_sin[idx] = (float)sin(ang);
}

// ---------------- RoPE apply + fp32->bf16 hi/lo split (q or k) ----------------
__global__ void rope_split_kernel(const float* __restrict__ t,
                                  __nv_bfloat16* __restrict__ hi,
                                  __nv_bfloat16* __restrict__ lo)
{
    const int NP = B_SZ * S_LEN * D_MODEL / 2;
    int idx = blockIdx.x * blockDim.x + threadIdx.x;
    if (idx >= NP) return;
    int d2 = idx & (D_MODEL / 2 - 1);
    int s  = (idx / (D_MODEL / 2)) & (S_LEN - 1);
    int i  = d2 & 63;
    float c  = g_cos[(s << 6) + i];
    float sn = g_sin[(s << 6) + i];
    float2 v = *(const float2*)(t + 2 * (size_t)idx);
    float r0 = v.x * c - v.y * sn;
    float r1 = v.x * sn + v.y * c;
    __nv_bfloat16 h0 = __float2bfloat16(r0);
    __nv_bfloat16 h1 = __float2bfloat16(r1);
    __nv_bfloat16 e0 = __float2bfloat16(r0 - __bfloat162float(h0));
    __nv_bfloat16 e1 = __float2bfloat16(r1 - __bfloat162float(h1));
    ushort2 hv, lv;
    hv.x = __bfloat16_as_ushort(h0); hv.y = __bfloat16_as_ushort(h1);
    lv.x = __bfloat16_as_ushort(e0); lv.y = __bfloat16_as_ushort(e1);
    ((ushort2*)hi)[idx] = hv;
    ((ushort2*)lo)[idx] = lv;
}

// ============== Flash attention (causal) with bf16x3 mma.sync ================
#define FAQ 64
#define FAK 32
#define FA_QHI 0
#define FA_QLO 16384
#define FA_STG 32768
#define FA_TILE 8192
#define FA_STAGE (4 * FA_TILE)
#define FA_SMEM (FA_STG + 2 * FA_STAGE)   // 98304

__device__ __forceinline__ void fa_issue_stage(
    uint32_t sb, int s, int k0, int tid,
    const __nv_bfloat16* kh, const __nv_bfloat16* kl,
    const __nv_bfloat16* vh, const __nv_bfloat16* vl)
{
    const uint32_t st = sb + FA_STG + (uint32_t)s * FA_STAGE;
    const __nv_bfloat16* gp[4];
    gp[0] = kh; gp[1] = kl; gp[2] = vh; gp[3] = vl;
#pragma unroll
    for (int t = 0; t < 4; t++) {
#pragma unroll
        for (int i = 0; i < 4; i++) {
            int idx = i * 128 + tid;
            int row = idx >> 4, ch = idx & 15;
            uint32_t dst = st + (uint32_t)t * FA_TILE
                         + SWZ256((uint32_t)(row * 256 + ch * 16));
            const char* src = (const char*)gp[t]
                            + (size_t)(k0 + row) * (D_MODEL * 2) + (size_t)ch * 16;
            cp16(dst, src);
        }
    }
    cp_commit();
}

__global__ __launch_bounds__(128, 2) void flash_attn_mma() {
    extern __shared__ char smraw[];
    const uint32_t sb = smem_u32(smraw);
    const int tid = threadIdx.x;
    const int lane = tid & 31;
    const int w = tid >> 5;
    const int qt = (int)gridDim.x - 1 - (int)blockIdx.x;
    const int bh = blockIdx.y;
    const int b = bh >> 4, h = bh & 15;
    const int q0 = qt * FAQ;
    const int n_kt = 2 * qt + 2;

    const size_t base = (size_t)b * S_LEN * D_MODEL + (size_t)h * HD;
    const __nv_bfloat16* qh = g_qh + base;
    const __nv_bfloat16* ql = g_ql + base;
    const __nv_bfloat16* kh = g_kh + base;
    const __nv_bfloat16* kl = g_kl + base;
    const __nv_bfloat16* vh = g_vh + base;
    const __nv_bfloat16* vl = g_vl + base;
    float* op = g_o + base;

#pragma unroll
    for (int i = 0; i < 8; i++) {
        int idx = i * 128 + tid;
        int row = idx >> 4, ch = idx & 15;
        uint32_t dsw = SWZ256((uint32_t)(row * 256 + ch * 16));
        const char* srch = (const char*)qh + (size_t)(q0 + row) * (D_MODEL * 2) + (size_t)ch * 16;
        const char* srcl = (const char*)ql + (size_t)(q0 + row) * (D_MODEL * 2) + (size_t)ch * 16;
        cp16(sb + FA_QHI + dsw, srch);
        cp16(sb + FA_QLO + dsw, srcl);
    }
    cp_commit();
    fa_issue_stage(sb, 0, 0, tid, kh, kl, vh, vl);
    fa_issue_stage(sb, 1, FAK, tid, kh, kl, vh, vl);

    const int g8 = lane >> 3;
    const int r8 = lane & 7;
    const int rowoff = (g8 & 1) * 8 + r8;
    const int qsel = g8 >> 1;

    float oacc[16][4];
#pragma unroll
    for (int t = 0; t < 16; t++) {
#pragma unroll
        for (int e = 0; e < 4; e++) { oacc[t][e] = 0.f; }
    }
    float m0 = -1e30f, m1 = -1e30f, l0 = 0.f, l1 = 0.f;
    const float sm_scale = 0.08838834764831843f;

    const int lrow0 = q0 + w * 16 + (lane >> 2);
    const int lcolb = (lane & 3) * 2;

    for (int kt = 0; kt < n_kt; kt++) {
        const int s = kt & 1;
        const int k0 = kt * FAK;
        CP_WAIT(1);
        __syncthreads();
        const uint32_t stg = sb + FA_STG + (uint32_t)s * FA_STAGE;

        float sacc[4][4];
#pragma unroll
        for (int t = 0; t < 4; t++) {
#pragma unroll
            for (int e = 0; e < 4; e++) { sacc[t][e] = 0.f; }
        }
#pragma unroll
        for (int ks = 0; ks < 8; ks++) {
            const int quad = ks * 2 + qsel;
            uint32_t qfh[4], qfl[4];
            const uint32_t qoff = SWZ256((uint32_t)((w * 16 + rowoff) * 256 + quad * 16));
            ldsm_x4(qfh, sb + FA_QHI + qoff);
            ldsm_x4(qfl, sb + FA_QLO + qoff);
#pragma unroll
            for (int nt = 0; nt < 2; nt++) {
                const uint32_t koff = SWZ256((uint32_t)((nt * 16 + rowoff) * 256 + quad * 16));
                uint32_t tkh[4], tkl[4];
                ldsm_x4(tkh, stg + koff);
                ldsm_x4(tkl, stg + FA_TILE + koff);
                uint32_t bh0[2], bh1[2], bl0[2], bl1[2];
                bh0[0] = tkh[0]; bh0[1] = tkh[2];
                bh1[0] = tkh[1]; bh1[1] = tkh[3];
                bl0[0] = tkl[0]; bl0[1] = tkl[2];
                bl1[0] = tkl[1]; bl1[1] = tkl[3];
                mma_bf16(sacc[nt * 2],     qfh, bh0);
                mma_bf16(sacc[nt * 2],     qfh, bl0);
                mma_bf16(sacc[nt * 2],     qfl, bh0);
                mma_bf16(sacc[nt * 2 + 1], qfh, bh1);
                mma_bf16(sacc[nt * 2 + 1], qfh, bl1);
                mma_bf16(sacc[nt * 2 + 1], qfl, bh1);
            }
        }

        const int need_mask = (k0 + FAK - 1 > q0 + w * 16) ? 1 : 0;
#pragma unroll
        for (int t = 0; t < 4; t++) {
#pragma unroll
            for (int e = 0; e < 4; e++) {
                float sv = sacc[t][e] * sm_scale;
                if (need_mask) {
                    int col = k0 + t * 8 + lcolb + (e & 1);
                    int row = lrow0 + ((e >> 1) & 1) * 8;
                    if (col > row) { sv = -1e30f; }
                }
                sacc[t][e] = sv;
            }
        }

        float rm0 = sacc[0][0], rm1 = sacc[0][2];
#pragma unroll
        for (int t = 0; t < 4; t++) {
            rm0 = fmaxf(rm0, fmaxf(sacc[t][0], sacc[t][1]));
            rm1 = fmaxf(rm1, fmaxf(sacc[t][2], sacc[t][3]));
        }
        rm0 = fmaxf(rm0, __shfl_xor_sync(0xffffffffu, rm0, 1));
        rm0 = fmaxf(rm0, __shfl_xor_sync(0xffffffffu, rm0, 2));
        rm1 = fmaxf(rm1, __shfl_xor_sync(0xffffffffu, rm1, 1));
        rm1 = fmaxf(rm1, __shfl_xor_sync(0xffffffffu, rm1, 2));
        float mn0 = fmaxf(m0, rm0);
        float mn1 = fmaxf(m1, rm1);
        float alpha0 = expf(m0 - mn0);
        float alpha1 = expf(m1 - mn1);
        float rs0 = 0.f, rs1 = 0.f;
#pragma unroll
        for (int t = 0; t < 4; t++) {
            float p0 = expf(sacc[t][0] - mn0);
            float p1 = expf(sacc[t][1] - mn0);
            float p2 = expf(sacc[t][2] - mn1);
            float p3 = expf(sacc[t][3] - mn1);
            rs0 += p0 + p1;
            rs1 += p2 + p3;
            sacc[t][0] = p0; sacc[t][1] = p1;
            sacc[t][2] = p2; sacc[t][3] = p3;
        }
        rs0 += __shfl_xor_sync(0xffffffffu, rs0, 1);
        rs0 += __shfl_xor_sync(0xffffffffu, rs0, 2);
        rs1 += __shfl_xor_sync(0xffffffffu, rs1, 1);
        rs1 += __shfl_xor_sync(0xffffffffu, rs1, 2);
        l0 = l0 * alpha0 + rs0;
        l1 = l1 * alpha1 + rs1;
        m0 = mn0; m1 = mn1;
#pragma unroll
        for (int t = 0; t < 16; t++) {
            oacc[t][0] *= alpha0; oacc[t][1] *= alpha0;
            oacc[t][2] *= alpha1; oacc[t][3] *= alpha1;
        }

        uint32_t pfh[2][4], pfl[2][4];
#pragma unroll
        for (int j = 0; j < 2; j++) {
#pragma unroll
            for (int idx = 0; idx < 4; idx++) {
                int st = 2 * j + (idx >> 1);
                int rp = (idx & 1) * 2;
                float f0 = sacc[st][rp];
                float f1 = sacc[st][rp + 1];
                __nv_bfloat16 h0 = __float2bfloat16(f0);
                __nv_bfloat16 h1 = __float2bfloat16(f1);
                float r0f = f0 - __bfloat162float(h0);
                float r1f = f1 - __bfloat162float(h1);
                __nv_bfloat16 e0 = __float2bfloat16(r0f);
                __nv_bfloat16 e1 = __float2bfloat16(r1f);
                pfh[j][idx] = (uint32_t)__bfloat16_as_ushort(h0)
                            | ((uint32_t)__bfloat16_as_ushort(h1) << 16);
                pfl[j][idx] = (uint32_t)__bfloat16_as_ushort(e0)
                            | ((uint32_t)__bfloat16_as_ushort(e1) << 16);
            }
        }

        const int vrow_base = (lane & 7) + ((lane >> 3) & 1) * 8;
        const int vcol_base = ((lane >> 4) & 1) * 16;
#pragma unroll
        for (int j = 0; j < 2; j++) {
#pragma unroll
            for (int nt = 0; nt < 8; nt++) {
                const int vr = j * 16 + vrow_base;
                const int vcb = nt * 32 + vcol_base;
                const uint32_t voff = SWZ256((uint32_t)(vr * 256 + vcb));
                uint32_t tvh[4], tvl[4];
                ldsm_x4_t(tvh, stg + 2 * FA_TILE + voff);
                ldsm_x4_t(tvl, stg + 3 * FA_TILE + voff);
                uint32_t bh0[2], bh1[2], bl0[2], bl1[2];
                bh0[0] = tvh[0]; bh0[1] = tvh[1];
                bh1[0] = tvh[2]; bh1[1] = tvh[3];
                bl0[0] = tvl[0]; bl0[1] = tvl[1];
                bl1[0] = tvl[2]; bl1[1] = tvl[3];
                mma_bf16(oacc[nt * 2],     pfh[j], bh0);
                mma_bf16(oacc[nt * 2],     pfh[j], bl0);
                mma_bf16(oacc[nt * 2],     pfl[j], bh0);
                mma_bf16(oacc[nt * 2 + 1], pfh[j], bh1);
                mma_bf16(oacc[nt * 2 + 1], pfh[j], bl1);
                mma_bf16(oacc[nt * 2 + 1], pfl[j], bh1);
            }
        }

        __syncthreads();
        if (kt + 2 < n_kt) {
            fa_issue_stage(sb, s, (kt + 2) * FAK, tid, kh, kl, vh, vl);
        } else {
            cp_commit();
        }
    }

    const float inv0 = 1.f / l0;
    const float inv1 = 1.f / l1;
#pragma unroll
    for (int t = 0; t < 16; t++) {
        const int col = t * 8 + lcolb;
        *(float2*)(op + (size_t)lrow0 * D_MODEL + col) =
            make_float2(oacc[t][0] * inv0, oacc[t][1] * inv0);
        *(float2*)(op + (size_t)(lrow0 + 8) * D_MODEL + col) =
            make_float2(oacc[t][2] * inv1, oacc[t][3] * inv1);
    }
}

// ======================= host side =======================
extern "C" void kernel_launch(void* const* d_in, const int* in_sizes, int n_in,
                              void* d_out, int out_size) {
    const float* x  = (const float*)d_in[0];
    const float* wq = (const float*)d_in[1];
    const float* wk = (const float*)d_in[2];
    const float* wv = (const float*)d_in[3];
    const float* wo = (const float*)d_in[4];
    float* out = (float*)d_out;

    float *q, *k, *v, *o;
    cudaGetSymbolAddress((void**)&q, g_q);
    cudaGetSymbolAddress((void**)&k, g_k);
    cudaGetSymbolAddress((void**)&v, g_v);
    cudaGetSymbolAddress((void**)&o, g_o);

    __half *xh2, *xl2, *oh2, *ol2, *wq16, *wk16, *wv16, *wo16;
    __nv_bfloat16 *qh, *ql, *kh, *kl, *vh, *vl;
    cudaGetSymbolAddress((void**)&xh2, g_xh2);  cudaGetSymbolAddress((void**)&xl2, g_xl2);
    cudaGetSymbolAddress((void**)&oh2, g_oh2);  cudaGetSymbolAddress((void**)&ol2, g_ol2);
    cudaGetSymbolAddress((void**)&wq16, g_wq16); cudaGetSymbolAddress((void**)&wk16, g_wk16);
    cudaGetSymbolAddress((void**)&wv16, g_wv16); cudaGetSymbolAddress((void**)&wo16, g_wo16);
    cudaGetSymbolAddress((void**)&qh, g_qh); cudaGetSymbolAddress((void**)&ql, g_ql);
    cudaGetSymbolAddress((void**)&kh, g_kh); cudaGetSymbolAddress((void**)&kl, g_kl);
    cudaGetSymbolAddress((void**)&vh, g_vh); cudaGetSymbolAddress((void**)&vl, g_vl);

    rope_table_kernel<<<(S_LEN * (HD / 2) + 255) / 256, 256>>>();

    const int xn4 = MROWS * D_MODEL / 4;
    const int wn4 = D_MODEL * D_MODEL / 4;
    split_f16_kernel<<<(xn4 + 255) / 256, 256>>>(x, xh2, xl2, xn4);
    cvt_f16_kernel<<<(wn4 + 255) / 256, 256>>>(wq, wq16, wn4);
    cvt_f16_kernel<<<(wn4 + 255) / 256, 256>>>(wk, wk16, wn4);
    cvt_f16_kernel<<<(wn4 + 255) / 256, 256>>>(wv, wv16, wn4);
    cvt_f16_kernel<<<(wn4 + 255) / 256, 256>>>(wo, wo16, wn4);

    cudaFuncSetAttribute(gemm_f16x2_tri, cudaFuncAttributeMaxDynamicSharedMemorySize, GEMM_SMEM);
    // fused Q/K/V projection: grid.x = 3 * 16 n-blocks
    gemm_f16x2_tri<<<dim3(48, MROWS / GBM), 256, GEMM_SMEM>>>(
        xh2, xl2, wq16, wk16, wv16, q, k, v);

    const int np = B_SZ * S_LEN * D_MODEL / 2;
    rope_split_kernel<<<(np + 255) / 256, 256>>>(q, qh, ql);
    rope_split_kernel<<<(np + 255) / 256, 256>>>(k, kh, kl);
    split_bf16_kernel<<<(xn4 + 255) / 256, 256>>>(v, vh, vl, xn4);

    cudaFuncSetAttribute(flash_attn_mma, cudaFuncAttributeMaxDynamicSharedMemorySize, FA_SMEM);
    flash_attn_mma<<<dim3(S_LEN / FAQ, B_SZ * NH), 128, FA_SMEM>>>();

    split_f16_kernel<<<(xn4 + 255) / 256, 256>>>(o, oh2, ol2, xn4);
    // output projection through the same kernel (single B/C)
    gemm_f16x2_tri<<<dim3(16, MROWS / GBM), 256, GEMM_SMEM>>>(
        oh2, ol2, wo16, wo16, wo16, out, out, out);
}

// round 9
// speedup vs baseline: 4.6533x; 1.0916x over previous
#include <cuda_runtime.h>
#include <cuda_fp16.h>
#include <stdint.h>
#include <math.h>

#define S_LEN 2048
#define B_SZ 2
#define D_MODEL 2048
#define NH 16
#define HD 128
#define MROWS (B_SZ * S_LEN)
#define KDIM 2048

// ---------------- scratch (static device allocations: allowed) ----------------
__device__ float g_cos[S_LEN * (HD / 2)];
__device__ float g_sin[S_LEN * (HD / 2)];

// fp16 split activations + fp16 weights
__device__ __half g_xh2[(size_t)MROWS * D_MODEL];
__device__ __half g_xl2[(size_t)MROWS * D_MODEL];
__device__ __half g_oh2[(size_t)MROWS * D_MODEL];
__device__ __half g_ol2[(size_t)MROWS * D_MODEL];
__device__ __half g_wq16[(size_t)D_MODEL * D_MODEL];
__device__ __half g_wk16[(size_t)D_MODEL * D_MODEL];
__device__ __half g_wv16[(size_t)D_MODEL * D_MODEL];
__device__ __half g_wo16[(size_t)D_MODEL * D_MODEL];

// fp16 attention operands (written by QKV GEMM epilogue, rope applied)
__device__ __half g_qh2a[(size_t)MROWS * D_MODEL];   // q hi
__device__ __half g_ql2a[(size_t)MROWS * D_MODEL];   // q lo
__device__ __half g_k16[(size_t)MROWS * D_MODEL];    // k (single fp16)
__device__ __half g_v16[(size_t)MROWS * D_MODEL];    // v (single fp16)

// ======================= low-level helpers ====================================
__device__ __forceinline__ uint32_t smem_u32(const void* p) {
    uint32_t a;
    asm("{ .reg .u64 t; cvta.to.shared.u64 t, %1; cvt.u32.u64 %0, t; }" : "=r"(a) : "l"(p));
    return a;
}
__device__ __forceinline__ void cp16(uint32_t dst, const void* src) {
    asm volatile("cp.async.cg.shared.global [%0], [%1], 16;" :: "r"(dst), "l"(src));
}
__device__ __forceinline__ void cp_commit() {
    asm volatile("cp.async.commit_group;" ::: "memory");
}
#define CP_WAIT(n) asm volatile("cp.async.wait_group " #n ";" ::: "memory")

__device__ __forceinline__ void ldsm_x4(uint32_t* r, uint32_t addr) {
    asm volatile("ldmatrix.sync.aligned.m8n8.x4.shared.b16 {%0,%1,%2,%3}, [%4];"
                 : "=r"(r[0]), "=r"(r[1]), "=r"(r[2]), "=r"(r[3]) : "r"(addr));
}
__device__ __forceinline__ void ldsm_x4_t(uint32_t* r, uint32_t addr) {
    asm volatile("ldmatrix.sync.aligned.m8n8.x4.trans.shared.b16 {%0,%1,%2,%3}, [%4];"
                 : "=r"(r[0]), "=r"(r[1]), "=r"(r[2]), "=r"(r[3]) : "r"(addr));
}
__device__ __forceinline__ void mma_f16(float* d, const uint32_t* a, const uint32_t* b) {
    asm volatile(
        "mma.sync.aligned.m16n8k16.row.col.f32.f16.f16.f32 "
        "{%0,%1,%2,%3}, {%4,%5,%6,%7}, {%8,%9}, {%0,%1,%2,%3};"
        : "+f"(d[0]), "+f"(d[1]), "+f"(d[2]), "+f"(d[3])
        : "r"(a[0]), "r"(a[1]), "r"(a[2]), "r"(a[3]), "r"(b[0]), "r"(b[1]));
}

#define SWZ(x) ((x) ^ (((x) >> 3) & 0x70))
#define SWZ256(x) ((x) ^ (((x) >> 4) & 0x70))

// =========== fp16x2 2-pass GEMM core: acc = (Ah+Al) @ Bf16^T =================
#define GBM 128
#define GBN 128
#define NCHUNK (KDIM / 64)
#define TILE_B (GBM * 128)
#define STAGE_B (3 * TILE_B)
#define GEMM_SMEM (2 * STAGE_B)   // 98304

__device__ __forceinline__ void gemm_issue2(
    const __half* Ah, const __half* Al, const __half* Bh,
    uint32_t sb0, int m0, int n0, int tid, int c, int s)
{
    const uint32_t st = sb0 + (uint32_t)s * STAGE_B;
    const size_t kb = (size_t)c * 128;
    const int lq = tid & 7;
#pragma unroll
    for (int i = 0; i < 4; i++) {
        const int r = (tid + i * 256) >> 3;
        const uint32_t dsw = SWZ((uint32_t)(r * 128 + lq * 16));
        const size_t arow = (size_t)(m0 + r) * (KDIM * 2) + kb + (size_t)lq * 16;
        const size_t brow = (size_t)(n0 + r) * (KDIM * 2) + kb + (size_t)lq * 16;
        cp16(st + dsw,              (const char*)Ah + arow);
        cp16(st + TILE_B + dsw,     (const char*)Al + arow);
        cp16(st + 2 * TILE_B + dsw, (const char*)Bh + brow);
    }
    cp_commit();
}

__device__ __forceinline__ void gemm_core(
    float acc[4][4][4],
    const __half* Ah, const __half* Al, const __half* Bh,
    uint32_t sb0, int m0, int n0)
{
    const int tid = threadIdx.x;
    const int wid = tid >> 5;
    const int lane = tid & 31;
    const int m_base = (wid >> 2) * 64;
    const int n_base = (wid & 3) * 32;

#pragma unroll
    for (int i = 0; i < 4; i++) {
#pragma unroll
        for (int j = 0; j < 4; j++) {
#pragma unroll
            for (int e = 0; e < 4; e++) { acc[i][j][e] = 0.f; }
        }
    }

    gemm_issue2(Ah, Al, Bh, sb0, m0, n0, tid, 0, 0);
    gemm_issue2(Ah, Al, Bh, sb0, m0, n0, tid, 1, 1);

    const int g8 = lane >> 3;
    const int r8 = lane & 7;
    const int rowoff = (g8 & 1) * 8 + r8;
    const int qhi = g8 >> 1;

    for (int c = 0; c < NCHUNK; c++) {
        const int s = c & 1;
        CP_WAIT(1);
        __syncthreads();
        const uint32_t sAh = sb0 + (uint32_t)s * STAGE_B;
        const uint32_t sAl = sAh + TILE_B;
        const uint32_t sBh = sAh + 2 * TILE_B;

#pragma unroll
        for (int ks = 0; ks < 4; ks++) {
            const int quad = ks * 2 + qhi;
            uint32_t ah[4][4], al[4][4], bh[4][2];
#pragma unroll
            for (int mi = 0; mi < 4; mi++) {
                const uint32_t off = SWZ((uint32_t)((m_base + mi * 16 + rowoff) * 128 + quad * 16));
                ldsm_x4(ah[mi], sAh + off);
                ldsm_x4(al[mi], sAl + off);
            }
#pragma unroll
            for (int p = 0; p < 2; p++) {
                const uint32_t off = SWZ((uint32_t)((n_base + p * 16 + rowoff) * 128 + quad * 16));
                uint32_t t[4];
                ldsm_x4(t, sBh + off);
                bh[2 * p][0] = t[0]; bh[2 * p][1] = t[2];
                bh[2 * p + 1][0] = t[1]; bh[2 * p + 1][1] = t[3];
            }
#pragma unroll
            for (int mi = 0; mi < 4; mi++) {
#pragma unroll
                for (int ni = 0; ni < 4; ni++) {
                    mma_f16(acc[mi][ni], ah[mi], bh[ni]);
                    mma_f16(acc[mi][ni], al[mi], bh[ni]);
                }
            }
        }
        __syncthreads();
        if (c + 2 < NCHUNK) {
            gemm_issue2(Ah, Al, Bh, sb0, m0, n0, tid, c + 2, s);
        }
    }
}

// ---- fused QKV projection: epilogue applies RoPE (q,k) + fp16 rounding ------
__global__ __launch_bounds__(256) void gemm_qkv(
    const __half* __restrict__ Ah, const __half* __restrict__ Al)
{
    extern __shared__ char smem[];
    const uint32_t sb0 = smem_u32(smem);

    const int nb = blockIdx.x;
    const int which = nb >> 4;               // 0=q, 1=k, 2=v
    const int n0 = (nb & 15) * GBN;
    const __half* Bh = (which == 0) ? g_wq16 : ((which == 1) ? g_wk16 : g_wv16);
    const int m0 = blockIdx.y * GBM;

    float acc[4][4][4];
    gemm_core(acc, Ah, Al, Bh, sb0, m0, n0);

    const int wid = threadIdx.x >> 5;
    const int lane = threadIdx.x & 31;
    const int m_base = (wid >> 2) * 64;
    const int n_base = (wid & 3) * 32;
    const int erow = lane >> 2;
    const int ecol = (lane & 3) * 2;

#pragma unroll
    for (int mi = 0; mi < 4; mi++) {
#pragma unroll
        for (int ni = 0; ni < 4; ni++) {
            const int row = m0 + m_base + mi * 16 + erow;
            const int col = n0 + n_base + ni * 8 + ecol;     // even
            float a0 = acc[mi][ni][0], a1 = acc[mi][ni][1];  // (row,   col..col+1)
            float b0 = acc[mi][ni][2], b1 = acc[mi][ni][3];  // (row+8, col..col+1)
            if (which < 2) {    // RoPE on q, k
                const int i = (col & 127) >> 1;
                const int s1 = row & (S_LEN - 1);
                const int s2 = (row + 8) & (S_LEN - 1);
                float c1 = g_cos[(s1 << 6) + i], sn1 = g_sin[(s1 << 6) + i];
                float c2 = g_cos[(s2 << 6) + i], sn2 = g_sin[(s2 << 6) + i];
                float t0 = a0 * c1 - a1 * sn1;
                float t1 = a0 * sn1 + a1 * c1;
                a0 = t0; a1 = t1;
                t0 = b0 * c2 - b1 * sn2;
                t1 = b0 * sn2 + b1 * c2;
                b0 = t0; b1 = t1;
            }
            const size_t off0 = (size_t)row * D_MODEL + col;
            const size_t off1 = (size_t)(row + 8) * D_MODEL + col;
            __half ha0 = __float2half_rn(a0);
            __half ha1 = __float2half_rn(a1);
            __half hb0 = __float2half_rn(b0);
            __half hb1 = __float2half_rn(b1);
            ushort2 va, vb;
            va.x = __half_as_ushort(ha0); va.y = __half_as_ushort(ha1);
            vb.x = __half_as_ushort(hb0); vb.y = __half_as_ushort(hb1);
            if (which == 0) {
                ((ushort2*)g_qh2a)[off0 >> 1] = va;
                ((ushort2*)g_qh2a)[off1 >> 1] = vb;
                __half la0 = __float2half_rn(a0 - __half2float(ha0));
                __half la1 = __float2half_rn(a1 - __half2float(ha1));
                __half lb0 = __float2half_rn(b0 - __half2float(hb0));
                __half lb1 = __float2half_rn(b1 - __half2float(hb1));
                ushort2 wa, wb;
                wa.x = __half_as_ushort(la0); wa.y = __half_as_ushort(la1);
                wb.x = __half_as_ushort(lb0); wb.y = __half_as_ushort(lb1);
                ((ushort2*)g_ql2a)[off0 >> 1] = wa;
                ((ushort2*)g_ql2a)[off1 >> 1] = wb;
            } else if (which == 1) {
                ((ushort2*)g_k16)[off0 >> 1] = va;
                ((ushort2*)g_k16)[off1 >> 1] = vb;
            } else {
                ((ushort2*)g_v16)[off0 >> 1] = va;
                ((ushort2*)g_v16)[off1 >> 1] = vb;
            }
        }
    }
}

// ---- output projection: fp32 epilogue to d_out ------------------------------
__global__ __launch_bounds__(256) void gemm_out(
    const __half* __restrict__ Ah, const __half* __restrict__ Al,
    const __half* __restrict__ Bh, float* __restrict__ C)
{
    extern __shared__ char smem[];
    const uint32_t sb0 = smem_u32(smem);
    const int n0 = blockIdx.x * GBN;
    const int m0 = blockIdx.y * GBM;

    float acc[4][4][4];
    gemm_core(acc, Ah, Al, Bh, sb0, m0, n0);

    const int wid = threadIdx.x >> 5;
    const int lane = threadIdx.x & 31;
    const int m_base = (wid >> 2) * 64;
    const int n_base = (wid & 3) * 32;
    const int erow = lane >> 2;
    const int ecol = (lane & 3) * 2;
#pragma unroll
    for (int mi = 0; mi < 4; mi++) {
#pragma unroll
        for (int ni = 0; ni < 4; ni++) {
            const int row = m0 + m_base + mi * 16 + erow;
            const int col = n0 + n_base + ni * 8 + ecol;
            *(float2*)(C + (size_t)row * D_MODEL + col) =
                make_float2(acc[mi][ni][0], acc[mi][ni][1]);
            *(float2*)(C + (size_t)(row + 8) * D_MODEL + col) =
                make_float2(acc[mi][ni][2], acc[mi][ni][3]);
        }
    }
}

// ---------------- fp32 -> (hi, lo) fp16 split ----------------
__global__ void split_f16_kernel(const float* __restrict__ src,
                                 __half* __restrict__ hi,
                                 __half* __restrict__ lo, int n4)
{
    int i = blockIdx.x * blockDim.x + threadIdx.x;
    if (i >= n4) return;
    float4 f = ((const float4*)src)[i];
    __half h0 = __float2half_rn(f.x);
    __half h1 = __float2half_rn(f.y);
    __half h2 = __float2half_rn(f.z);
    __half h3 = __float2half_rn(f.w);
    __half l0 = __float2half_rn(f.x - __half2float(h0));
    __half l1 = __float2half_rn(f.y - __half2float(h1));
    __half l2 = __float2half_rn(f.z - __half2float(h2));
    __half l3 = __float2half_rn(f.w - __half2float(h3));
    ushort4 hv, lv;
    hv.x = __half_as_ushort(h0); hv.y = __half_as_ushort(h1);
    hv.z = __half_as_ushort(h2); hv.w = __half_as_ushort(h3);
    lv.x = __half_as_ushort(l0); lv.y = __half_as_ushort(l1);
    lv.z = __half_as_ushort(l2); lv.w = __half_as_ushort(l3);
    ((ushort4*)hi)[i] = hv;
    ((ushort4*)lo)[i] = lv;
}

// ---------------- fp32 -> fp16 convert (weights) ----------------
__global__ void cvt_f16_kernel(const float* __restrict__ src,
                               __half* __restrict__ dst, int n4)
{
    int i = blockIdx.x * blockDim.x + threadIdx.x;
    if (i >= n4) return;
    float4 f = ((const float4*)src)[i];
    ushort4 hv;
    hv.x = __half_as_ushort(__float2half_rn(f.x));
    hv.y = __half_as_ushort(__float2half_rn(f.y));
    hv.z = __half_as_ushort(__float2half_rn(f.z));
    hv.w = __half_as_ushort(__float2half_rn(f.w));
    ((ushort4*)dst)[i] = hv;
}

// ---------------- RoPE table (double precision angles) ----------------
__global__ void rope_table_kernel() {
    int idx = blockIdx.x * blockDim.x + threadIdx.x;
    if (idx >= S_LEN * (HD / 2)) return;
    int s = idx >> 6;
    int i = idx & 63;
    double freq = exp(-log(10000.0) * (double)(2 * i) / (double)HD);
    double ang = (double)s * freq;
    g_cos[idx] = (float)cos(ang);
    g_sin[idx] = (float)sin(ang);
}

// ============== Flash attention (causal) fp16: QK 2-pass, PV 1-pass ==========
#define FAQ 64
#define FAK 32
#define FA_QHI 0
#define FA_QLO 16384
#define FA_STG 32768
#define FA_TILE 8192                  // K or V tile: 32 rows x 256B
#define FA_STAGE (2 * FA_TILE)        // 16KB
#define FA_SMEM (FA_STG + 2 * FA_STAGE)   // 65536

__device__ __forceinline__ void fa_issue_stage(
    uint32_t sb, int s, int k0, int tid,
    const __half* kp, const __half* vp)
{
    const uint32_t st = sb + FA_STG + (uint32_t)s * FA_STAGE;
#pragma unroll
    for (int i = 0; i < 4; i++) {
        int idx = i * 128 + tid;
        int row = idx >> 4, ch = idx & 15;
        uint32_t dsw = SWZ256((uint32_t)(row * 256 + ch * 16));
        const char* srck = (const char*)kp + (size_t)(k0 + row) * (D_MODEL * 2) + (size_t)ch * 16;
        const char* srcv = (const char*)vp + (size_t)(k0 + row) * (D_MODEL * 2) + (size_t)ch * 16;
        cp16(st + dsw,           srck);
        cp16(st + FA_TILE + dsw, srcv);
    }
    cp_commit();
}

__global__ __launch_bounds__(128, 2) void flash_attn_mma() {
    extern __shared__ char smraw[];
    const uint32_t sb = smem_u32(smraw);
    const int tid = threadIdx.x;
    const int lane = tid & 31;
    const int w = tid >> 5;
    const int qt = (int)gridDim.x - 1 - (int)blockIdx.x;
    const int bh = blockIdx.y;
    const int b = bh >> 4, h = bh & 15;
    const int q0 = qt * FAQ;
    const int n_kt = 2 * qt + 2;

    const size_t base = (size_t)b * S_LEN * D_MODEL + (size_t)h * HD;
    const __half* qhp = g_qh2a + base;
    const __half* qlp = g_ql2a + base;
    const __half* kp  = g_k16 + base;
    const __half* vp  = g_v16 + base;
    __half* oph = g_oh2 + base;
    __half* opl = g_ol2 + base;

#pragma unroll
    for (int i = 0; i < 8; i++) {
        int idx = i * 128 + tid;
        int row = idx >> 4, ch = idx & 15;
        uint32_t dsw = SWZ256((uint32_t)(row * 256 + ch * 16));
        const char* srch = (const char*)qhp + (size_t)(q0 + row) * (D_MODEL * 2) + (size_t)ch * 16;
        const char* srcl = (const char*)qlp + (size_t)(q0 + row) * (D_MODEL * 2) + (size_t)ch * 16;
        cp16(sb + FA_QHI + dsw, srch);
        cp16(sb + FA_QLO + dsw, srcl);
    }
    cp_commit();
    fa_issue_stage(sb, 0, 0, tid, kp, vp);
    fa_issue_stage(sb, 1, FAK, tid, kp, vp);

    const int g8 = lane >> 3;
    const int r8 = lane & 7;
    const int rowoff = (g8 & 1) * 8 + r8;
    const int qsel = g8 >> 1;

    float oacc[16][4];
#pragma unroll
    for (int t = 0; t < 16; t++) {
#pragma unroll
        for (int e = 0; e < 4; e++) { oacc[t][e] = 0.f; }
    }
    float m0 = -1e30f, m1 = -1e30f, l0 = 0.f, l1 = 0.f;
    const float sm_scale = 0.08838834764831843f;

    const int lrow0 = q0 + w * 16 + (lane >> 2);
    const int lcolb = (lane & 3) * 2;

    for (int kt = 0; kt < n_kt; kt++) {
        const int s = kt & 1;
        const int k0 = kt * FAK;
        CP_WAIT(1);
        __syncthreads();
        const uint32_t stg = sb + FA_STG + (uint32_t)s * FA_STAGE;

        // ---- S = Q @ K^T : 2-pass (Qh + Ql) x Kf16 ----
        float sacc[4][4];
#pragma unroll
        for (int t = 0; t < 4; t++) {
#pragma unroll
            for (int e = 0; e < 4; e++) { sacc[t][e] = 0.f; }
        }
#pragma unroll
        for (int ks = 0; ks < 8; ks++) {
            const int quad = ks * 2 + qsel;
            uint32_t qfh[4], qfl[4];
            const uint32_t qoff = SWZ256((uint32_t)((w * 16 + rowoff) * 256 + quad * 16));
            ldsm_x4(qfh, sb + FA_QHI + qoff);
            ldsm_x4(qfl, sb + FA_QLO + qoff);
#pragma unroll
            for (int nt = 0; nt < 2; nt++) {
                const uint32_t koff = SWZ256((uint32_t)((nt * 16 + rowoff) * 256 + quad * 16));
                uint32_t tk[4];
                ldsm_x4(tk, stg + koff);
                uint32_t b0[2], b1[2];
                b0[0] = tk[0]; b0[1] = tk[2];
                b1[0] = tk[1]; b1[1] = tk[3];
                mma_f16(sacc[nt * 2],     qfh, b0);
                mma_f16(sacc[nt * 2],     qfl, b0);
                mma_f16(sacc[nt * 2 + 1], qfh, b1);
                mma_f16(sacc[nt * 2 + 1], qfl, b1);
            }
        }

        // ---- scale + causal mask ----
        const int need_mask = (k0 + FAK - 1 > q0 + w * 16) ? 1 : 0;
#pragma unroll
        for (int t = 0; t < 4; t++) {
#pragma unroll
            for (int e = 0; e < 4; e++) {
                float sv = sacc[t][e] * sm_scale;
                if (need_mask) {
                    int col = k0 + t * 8 + lcolb + (e & 1);
                    int row = lrow0 + ((e >> 1) & 1) * 8;
                    if (col > row) { sv = -1e30f; }
                }
                sacc[t][e] = sv;
            }
        }

        // ---- online softmax ----
        float rm0 = sacc[0][0], rm1 = sacc[0][2];
#pragma unroll
        for (int t = 0; t < 4; t++) {
            rm0 = fmaxf(rm0, fmaxf(sacc[t][0], sacc[t][1]));
            rm1 = fmaxf(rm1, fmaxf(sacc[t][2], sacc[t][3]));
        }
        rm0 = fmaxf(rm0, __shfl_xor_sync(0xffffffffu, rm0, 1));
        rm0 = fmaxf(rm0, __shfl_xor_sync(0xffffffffu, rm0, 2));
        rm1 = fmaxf(rm1, __shfl_xor_sync(0xffffffffu, rm1, 1));
        rm1 = fmaxf(rm1, __shfl_xor_sync(0xffffffffu, rm1, 2));
        float mn0 = fmaxf(m0, rm0);
        float mn1 = fmaxf(m1, rm1);
        float alpha0 = expf(m0 - mn0);
        float alpha1 = expf(m1 - mn1);
        float rs0 = 0.f, rs1 = 0.f;
#pragma unroll
        for (int t = 0; t < 4; t++) {
            float p0 = expf(sacc[t][0] - mn0);
            float p1 = expf(sacc[t][1] - mn0);
            float p2 = expf(sacc[t][2] - mn1);
            float p3 = expf(sacc[t][3] - mn1);
            rs0 += p0 + p1;
            rs1 += p2 + p3;
            sacc[t][0] = p0; sacc[t][1] = p1;
            sacc[t][2] = p2; sacc[t][3] = p3;
        }
        rs0 += __shfl_xor_sync(0xffffffffu, rs0, 1);
        rs0 += __shfl_xor_sync(0xffffffffu, rs0, 2);
        rs1 += __shfl_xor_sync(0xffffffffu, rs1, 1);
        rs1 += __shfl_xor_sync(0xffffffffu, rs1, 2);
        l0 = l0 * alpha0 + rs0;
        l1 = l1 * alpha1 + rs1;
        m0 = mn0; m1 = mn1;
#pragma unroll
        for (int t = 0; t < 16; t++) {
            oacc[t][0] *= alpha0; oacc[t][1] *= alpha0;
            oacc[t][2] *= alpha1; oacc[t][3] *= alpha1;
        }

        // ---- pack P to fp16 A-frags (single precision pass suffices) ----
        uint32_t pf[2][4];
#pragma unroll
        for (int j = 0; j < 2; j++) {
#pragma unroll
            for (int idx = 0; idx < 4; idx++) {
                int st = 2 * j + (idx >> 1);
                int rp = (idx & 1) * 2;
                __half p0 = __float2half_rn(sacc[st][rp]);
                __half p1 = __float2half_rn(sacc[st][rp + 1]);
                pf[j][idx] = (uint32_t)__half_as_ushort(p0)
                           | ((uint32_t)__half_as_ushort(p1) << 16);
            }
        }

        // ---- O += P @ V : single pass fp16 ----
        const int vrow_base = (lane & 7) + ((lane >> 3) & 1) * 8;
        const int vcol_base = ((lane >> 4) & 1) * 16;
#pragma unroll
        for (int j = 0; j < 2; j++) {
#pragma unroll
            for (int nt = 0; nt < 8; nt++) {
                const int vr = j * 16 + vrow_base;
                const int vcb = nt * 32 + vcol_base;
                const uint32_t voff = SWZ256((uint32_t)(vr * 256 + vcb));
                uint32_t tv[4];
                ldsm_x4_t(tv, stg + FA_TILE + voff);
                uint32_t b0[2], b1[2];
                b0[0] = tv[0]; b0[1] = tv[1];
                b1[0] = tv[2]; b1[1] = tv[3];
                mma_f16(oacc[nt * 2],     pf[j], b0);
                mma_f16(oacc[nt * 2 + 1], pf[j], b1);
            }
        }

        __syncthreads();
        if (kt + 2 < n_kt) {
            fa_issue_stage(sb, s, (kt + 2) * FAK, tid, kp, vp);
        } else {
            cp_commit();
        }
    }

    // ---- epilogue: normalize, fp16 hi/lo split, store ----
    const float inv0 = 1.f / l0;
    const float inv1 = 1.f / l1;
#pragma unroll
    for (int t = 0; t < 16; t++) {
        const int col = t * 8 + lcolb;
        const size_t off0 = (size_t)lrow0 * D_MODEL + col;
        const size_t off1 = (size_t)(lrow0 + 8) * D_MODEL + col;
        float o0 = oacc[t][0] * inv0;
        float o1 = oacc[t][1] * inv0;
        float o2 = oacc[t][2] * inv1;
        float o3 = oacc[t][3] * inv1;
        __half h0 = __float2half_rn(o0);
        __half h1 = __float2half_rn(o1);
        __half h2 = __float2half_rn(o2);
        __half h3 = __float2half_rn(o3);
        ushort2 a, bq, c, d;
        a.x = __half_as_ushort(h0); a.y = __half_as_ushort(h1);
        bq.x = __half_as_ushort(h2); bq.y = __half_as_ushort(h3);
        c.x = __half_as_ushort(__float2half_rn(o0 - __half2float(h0)));
        c.y = __half_as_ushort(__float2half_rn(o1 - __half2float(h1)));
        d.x = __half_as_ushort(__float2half_rn(o2 - __half2float(h2)));
        d.y = __half_as_ushort(__float2half_rn(o3 - __half2float(h3)));
        ((ushort2*)oph)[off0 >> 1] = a;
        ((ushort2*)oph)[off1 >> 1] = bq;
        ((ushort2*)opl)[off0 >> 1] = c;
        ((ushort2*)opl)[off1 >> 1] = d;
    }
}

// ======================= host side =======================
extern "C" void kernel_launch(void* const* d_in, const int* in_sizes, int n_in,
                              void* d_out, int out_size) {
    const float* x  = (const float*)d_in[0];
    const float* wq = (const float*)d_in[1];
    const float* wk = (const float*)d_in[2];
    const float* wv = (const float*)d_in[3];
    const float* wo = (const float*)d_in[4];
    float* out = (float*)d_out;

    __half *xh2, *xl2, *oh2, *ol2, *wq16, *wk16, *wv16, *wo16;
    cudaGetSymbolAddress((void**)&xh2, g_xh2);  cudaGetSymbolAddress((void**)&xl2, g_xl2);
    cudaGetSymbolAddress((void**)&oh2, g_oh2);  cudaGetSymbolAddress((void**)&ol2, g_ol2);
    cudaGetSymbolAddress((void**)&wq16, g_wq16); cudaGetSymbolAddress((void**)&wk16, g_wk16);
    cudaGetSymbolAddress((void**)&wv16, g_wv16); cudaGetSymbolAddress((void**)&wo16, g_wo16);

    rope_table_kernel<<<(S_LEN * (HD / 2) + 255) / 256, 256>>>();

    const int xn4 = MROWS * D_MODEL / 4;
    const int wn4 = D_MODEL * D_MODEL / 4;
    split_f16_kernel<<<(xn4 + 255) / 256, 256>>>(x, xh2, xl2, xn4);
    cvt_f16_kernel<<<(wn4 + 255) / 256, 256>>>(wq, wq16, wn4);
    cvt_f16_kernel<<<(wn4 + 255) / 256, 256>>>(wk, wk16, wn4);
    cvt_f16_kernel<<<(wn4 + 255) / 256, 256>>>(wv, wv16, wn4);
    cvt_f16_kernel<<<(wn4 + 255) / 256, 256>>>(wo, wo16, wn4);

    cudaFuncSetAttribute(gemm_qkv, cudaFuncAttributeMaxDynamicSharedMemorySize, GEMM_SMEM);
    cudaFuncSetAttribute(gemm_out, cudaFuncAttributeMaxDynamicSharedMemorySize, GEMM_SMEM);

    // fused Q/K/V projection with RoPE + fp16 epilogue
    gemm_qkv<<<dim3(48, MROWS / GBM), 256, GEMM_SMEM>>>(xh2, xl2);

    cudaFuncSetAttribute(flash_attn_mma, cudaFuncAttributeMaxDynamicSharedMemorySize, FA_SMEM);
    flash_attn_mma<<<dim3(S_LEN / FAQ, B_SZ * NH), 128, FA_SMEM>>>();

    gemm_out<<<dim3(16, MROWS / GBM), 256, GEMM_SMEM>>>(oh2, ol2, wo16, out);
}

// round 11
// speedup vs baseline: 7.6685x; 1.6480x over previous
#include <cuda_runtime.h>
#include <cuda_fp16.h>
#include <stdint.h>
#include <math.h>

#define S_LEN 2048
#define B_SZ 2
#define D_MODEL 2048
#define NH 16
#define HD 128
#define MROWS (B_SZ * S_LEN)
#define KDIM 2048

// ---------------- scratch (static device allocations: allowed) ----------------
__device__ float g_cos[S_LEN * (HD / 2)];
__device__ float g_sin[S_LEN * (HD / 2)];

__device__ __half g_x16[(size_t)MROWS * D_MODEL];
__device__ __half g_o16[(size_t)MROWS * D_MODEL];
__device__ __half g_wq16[(size_t)D_MODEL * D_MODEL];
__device__ __half g_wk16[(size_t)D_MODEL * D_MODEL];
__device__ __half g_wv16[(size_t)D_MODEL * D_MODEL];
__device__ __half g_wo16[(size_t)D_MODEL * D_MODEL];

// fp16 attention operands (written by QKV GEMM epilogue, rope applied)
__device__ __half g_qh2a[(size_t)MROWS * D_MODEL];   // q hi
__device__ __half g_ql2a[(size_t)MROWS * D_MODEL];   // q lo
__device__ __half g_k16[(size_t)MROWS * D_MODEL];    // k
__device__ __half g_v16[(size_t)MROWS * D_MODEL];    // v

// ======================= low-level helpers ====================================
__device__ __forceinline__ uint32_t smem_u32(const void* p) {
    uint32_t a;
    asm("{ .reg .u64 t; cvta.to.shared.u64 t, %1; cvt.u32.u64 %0, t; }" : "=r"(a) : "l"(p));
    return a;
}
__device__ __forceinline__ void cp16(uint32_t dst, const void* src) {
    asm volatile("cp.async.cg.shared.global [%0], [%1], 16;" :: "r"(dst), "l"(src));
}
__device__ __forceinline__ void cp_commit() {
    asm volatile("cp.async.commit_group;" ::: "memory");
}
#define CP_WAIT(n) asm volatile("cp.async.wait_group " #n ";" ::: "memory")

__device__ __forceinline__ void ldsm_x4(uint32_t* r, uint32_t addr) {
    asm volatile("ldmatrix.sync.aligned.m8n8.x4.shared.b16 {%0,%1,%2,%3}, [%4];"
                 : "=r"(r[0]), "=r"(r[1]), "=r"(r[2]), "=r"(r[3]) : "r"(addr));
}
__device__ __forceinline__ void ldsm_x4_t(uint32_t* r, uint32_t addr) {
    asm volatile("ldmatrix.sync.aligned.m8n8.x4.trans.shared.b16 {%0,%1,%2,%3}, [%4];"
                 : "=r"(r[0]), "=r"(r[1]), "=r"(r[2]), "=r"(r[3]) : "r"(addr));
}
__device__ __forceinline__ void mma_f16(float* d, const uint32_t* a, const uint32_t* b) {
    asm volatile(
        "mma.sync.aligned.m16n8k16.row.col.f32.f16.f16.f32 "
        "{%0,%1,%2,%3}, {%4,%5,%6,%7}, {%8,%9}, {%0,%1,%2,%3};"
        : "+f"(d[0]), "+f"(d[1]), "+f"(d[2]), "+f"(d[3])
        : "r"(a[0]), "r"(a[1]), "r"(a[2]), "r"(a[3]), "r"(b[0]), "r"(b[1]));
}

#define SWZ(x) ((x) ^ (((x) >> 3) & 0x70))
#define SWZ256(x) ((x) ^ (((x) >> 4) & 0x70))

// =========== fp16 1-pass GEMM core: acc = Af16 @ Bf16^T ======================
#define GBM 128
#define GBN 128
#define NCHUNK (KDIM / 64)
#define TILE_B (GBM * 128)
#define STAGE_B (2 * TILE_B)      // A, B tiles
#define GEMM_SMEM (2 * STAGE_B)   // 65536 -> 2 CTAs/SM feasible

__device__ __forceinline__ void gemm_issue1(
    const __half* Ah, const __half* Bh,
    uint32_t sb0, int m0, int n0, int tid, int c, int s)
{
    const uint32_t st = sb0 + (uint32_t)s * STAGE_B;
    const size_t kb = (size_t)c * 128;
    const int lq = tid & 7;
#pragma unroll
    for (int i = 0; i < 4; i++) {
        const int r = (tid + i * 256) >> 3;
        const uint32_t dsw = SWZ((uint32_t)(r * 128 + lq * 16));
        const size_t arow = (size_t)(m0 + r) * (KDIM * 2) + kb + (size_t)lq * 16;
        const size_t brow = (size_t)(n0 + r) * (KDIM * 2) + kb + (size_t)lq * 16;
        cp16(st + dsw,          (const char*)Ah + arow);
        cp16(st + TILE_B + dsw, (const char*)Bh + brow);
    }
    cp_commit();
}

__device__ __forceinline__ void gemm_core(
    float acc[4][4][4],
    const __half* Ah, const __half* Bh,
    uint32_t sb0, int m0, int n0)
{
    const int tid = threadIdx.x;
    const int wid = tid >> 5;
    const int lane = tid & 31;
    const int m_base = (wid >> 2) * 64;
    const int n_base = (wid & 3) * 32;

#pragma unroll
    for (int i = 0; i < 4; i++) {
#pragma unroll
        for (int j = 0; j < 4; j++) {
#pragma unroll
            for (int e = 0; e < 4; e++) { acc[i][j][e] = 0.f; }
        }
    }

    gemm_issue1(Ah, Bh, sb0, m0, n0, tid, 0, 0);
    gemm_issue1(Ah, Bh, sb0, m0, n0, tid, 1, 1);

    const int g8 = lane >> 3;
    const int r8 = lane & 7;
    const int rowoff = (g8 & 1) * 8 + r8;
    const int qhi = g8 >> 1;

    for (int c = 0; c < NCHUNK; c++) {
        const int s = c & 1;
        CP_WAIT(1);
        __syncthreads();
        const uint32_t sA = sb0 + (uint32_t)s * STAGE_B;
        const uint32_t sB = sA + TILE_B;

#pragma unroll
        for (int ks = 0; ks < 4; ks++) {
            const int quad = ks * 2 + qhi;
            uint32_t ah[4][4], bh[4][2];
#pragma unroll
            for (int mi = 0; mi < 4; mi++) {
                const uint32_t off = SWZ((uint32_t)((m_base + mi * 16 + rowoff) * 128 + quad * 16));
                ldsm_x4(ah[mi], sA + off);
            }
#pragma unroll
            for (int p = 0; p < 2; p++) {
                const uint32_t off = SWZ((uint32_t)((n_base + p * 16 + rowoff) * 128 + quad * 16));
                uint32_t t[4];
                ldsm_x4(t, sB + off);
                bh[2 * p][0] = t[0]; bh[2 * p][1] = t[2];
                bh[2 * p + 1][0] = t[1]; bh[2 * p + 1][1] = t[3];
            }
#pragma unroll
            for (int mi = 0; mi < 4; mi++) {
#pragma unroll
                for (int ni = 0; ni < 4; ni++) {
                    mma_f16(acc[mi][ni], ah[mi], bh[ni]);
                }
            }
        }
        __syncthreads();
        if (c + 2 < NCHUNK) {
            gemm_issue1(Ah, Bh, sb0, m0, n0, tid, c + 2, s);
        }
    }
}

// ---- fused QKV projection: epilogue applies RoPE (q,k) + fp16 rounding ------
__global__ __launch_bounds__(256) void gemm_qkv(const __half* __restrict__ Ah)
{
    extern __shared__ char smem[];
    const uint32_t sb0 = smem_u32(smem);

    const int nb = blockIdx.x;
    const int which = nb >> 4;               // 0=q, 1=k, 2=v
    const int n0 = (nb & 15) * GBN;
    const __half* Bh = (which == 0) ? g_wq16 : ((which == 1) ? g_wk16 : g_wv16);
    const int m0 = blockIdx.y * GBM;

    float acc[4][4][4];
    gemm_core(acc, Ah, Bh, sb0, m0, n0);

    const int wid = threadIdx.x >> 5;
    const int lane = threadIdx.x & 31;
    const int m_base = (wid >> 2) * 64;
    const int n_base = (wid & 3) * 32;
    const int erow = lane >> 2;
    const int ecol = (lane & 3) * 2;

#pragma unroll
    for (int mi = 0; mi < 4; mi++) {
#pragma unroll
        for (int ni = 0; ni < 4; ni++) {
            const int row = m0 + m_base + mi * 16 + erow;
            const int col = n0 + n_base + ni * 8 + ecol;     // even
            float a0 = acc[mi][ni][0], a1 = acc[mi][ni][1];
            float b0 = acc[mi][ni][2], b1 = acc[mi][ni][3];
            if (which < 2) {    // RoPE on q, k
                const int i = (col & 127) >> 1;
                const int s1 = row & (S_LEN - 1);
                const int s2 = (row + 8) & (S_LEN - 1);
                float c1 = g_cos[(s1 << 6) + i], sn1 = g_sin[(s1 << 6) + i];
                float c2 = g_cos[(s2 << 6) + i], sn2 = g_sin[(s2 << 6) + i];
                float t0 = a0 * c1 - a1 * sn1;
                float t1 = a0 * sn1 + a1 * c1;
                a0 = t0; a1 = t1;
                t0 = b0 * c2 - b1 * sn2;
                t1 = b0 * sn2 + b1 * c2;
                b0 = t0; b1 = t1;
            }
            const size_t off0 = (size_t)row * D_MODEL + col;
            const size_t off1 = (size_t)(row + 8) * D_MODEL + col;
            __half ha0 = __float2half_rn(a0);
            __half ha1 = __float2half_rn(a1);
            __half hb0 = __float2half_rn(b0);
            __half hb1 = __float2half_rn(b1);
            ushort2 va, vb;
            va.x = __half_as_ushort(ha0); va.y = __half_as_ushort(ha1);
            vb.x = __half_as_ushort(hb0); vb.y = __half_as_ushort(hb1);
            if (which == 0) {
                ((ushort2*)g_qh2a)[off0 >> 1] = va;
                ((ushort2*)g_qh2a)[off1 >> 1] = vb;
                __half la0 = __float2half_rn(a0 - __half2float(ha0));
                __half la1 = __float2half_rn(a1 - __half2float(ha1));
                __half lb0 = __float2half_rn(b0 - __half2float(hb0));
                __half lb1 = __float2half_rn(b1 - __half2float(hb1));
                ushort2 wa, wb;
                wa.x = __half_as_ushort(la0); wa.y = __half_as_ushort(la1);
                wb.x = __half_as_ushort(lb0); wb.y = __half_as_ushort(lb1);
                ((ushort2*)g_ql2a)[off0 >> 1] = wa;
                ((ushort2*)g_ql2a)[off1 >> 1] = wb;
            } else if (which == 1) {
                ((ushort2*)g_k16)[off0 >> 1] = va;
                ((ushort2*)g_k16)[off1 >> 1] = vb;
            } else {
                ((ushort2*)g_v16)[off0 >> 1] = va;
                ((ushort2*)g_v16)[off1 >> 1] = vb;
            }
        }
    }
}

// ---- output projection: fp32 epilogue to d_out ------------------------------
__global__ __launch_bounds__(256) void gemm_out(
    const __half* __restrict__ Ah,
    const __half* __restrict__ Bh, float* __restrict__ C)
{
    extern __shared__ char smem[];
    const uint32_t sb0 = smem_u32(smem);
    const int n0 = blockIdx.x * GBN;
    const int m0 = blockIdx.y * GBM;

    float acc[4][4][4];
    gemm_core(acc, Ah, Bh, sb0, m0, n0);

    const int wid = threadIdx.x >> 5;
    const int lane = threadIdx.x & 31;
    const int m_base = (wid >> 2) * 64;
    const int n_base = (wid & 3) * 32;
    const int erow = lane >> 2;
    const int ecol = (lane & 3) * 2;
#pragma unroll
    for (int mi = 0; mi < 4; mi++) {
#pragma unroll
        for (int ni = 0; ni < 4; ni++) {
            const int row = m0 + m_base + mi * 16 + erow;
            const int col = n0 + n_base + ni * 8 + ecol;
            *(float2*)(C + (size_t)row * D_MODEL + col) =
                make_float2(acc[mi][ni][0], acc[mi][ni][1]);
            *(float2*)(C + (size_t)(row + 8) * D_MODEL + col) =
                make_float2(acc[mi][ni][2], acc[mi][ni][3]);
        }
    }
}

// ---------------- fp32 -> fp16 convert ----------------
__global__ void cvt_f16_kernel(const float* __restrict__ src,
                               __half* __restrict__ dst, int n4)
{
    int i = blockIdx.x * blockDim.x + threadIdx.x;
    if (i >= n4) return;
    float4 f = ((const float4*)src)[i];
    ushort4 hv;
    hv.x = __half_as_ushort(__float2half_rn(f.x));
    hv.y = __half_as_ushort(__float2half_rn(f.y));
    hv.z = __half_as_ushort(__float2half_rn(f.z));
    hv.w = __half_as_ushort(__float2half_rn(f.w));
    ((ushort4*)dst)[i] = hv;
}

// ---------------- RoPE table (double precision angles) ----------------
__global__ void rope_table_kernel() {
    int idx = blockIdx.x * blockDim.x + threadIdx.x;
    if (idx >= S_LEN * (HD / 2)) return;
    int s = idx >> 6;
    int i = idx & 63;
    double freq = exp(-log(10000.0) * (double)(2 * i) / (double)HD);
    double ang = (double)s * freq;
    g_cos[idx] = (float)cos(ang);
    g_sin[idx] = (float)sin(ang);
}

// ============== Flash attention (causal) fp16: QK 2-pass, PV 1-pass ==========
#define FAQ 64
#define FAK 32
#define FA_QHI 0
#define FA_QLO 16384
#define FA_STG 32768
#define FA_TILE 8192
#define FA_STAGE (2 * FA_TILE)
#define FA_SMEM (FA_STG + 2 * FA_STAGE)   // 65536

__device__ __forceinline__ void fa_issue_stage(
    uint32_t sb, int s, int k0, int tid,
    const __half* kp, const __half* vp)
{
    const uint32_t st = sb + FA_STG + (uint32_t)s * FA_STAGE;
#pragma unroll
    for (int i = 0; i < 4; i++) {
        int idx = i * 128 + tid;
        int row = idx >> 4, ch = idx & 15;
        uint32_t dsw = SWZ256((uint32_t)(row * 256 + ch * 16));
        const char* srck = (const char*)kp + (size_t)(k0 + row) * (D_MODEL * 2) + (size_t)ch * 16;
        const char* srcv = (const char*)vp + (size_t)(k0 + row) * (D_MODEL * 2) + (size_t)ch * 16;
        cp16(st + dsw,           srck);
        cp16(st + FA_TILE + dsw, srcv);
    }
    cp_commit();
}

__global__ __launch_bounds__(128, 2) void flash_attn_mma() {
    extern __shared__ char smraw[];
    const uint32_t sb = smem_u32(smraw);
    const int tid = threadIdx.x;
    const int lane = tid & 31;
    const int w = tid >> 5;
    const int qt = (int)gridDim.x - 1 - (int)blockIdx.x;
    const int bh = blockIdx.y;
    const int b = bh >> 4, h = bh & 15;
    const int q0 = qt * FAQ;
    const int n_kt = 2 * qt + 2;

    const size_t base = (size_t)b * S_LEN * D_MODEL + (size_t)h * HD;
    const __half* qhp = g_qh2a + base;
    const __half* qlp = g_ql2a + base;
    const __half* kp  = g_k16 + base;
    const __half* vp  = g_v16 + base;
    __half* oph = g_o16 + base;

#pragma unroll
    for (int i = 0; i < 8; i++) {
        int idx = i * 128 + tid;
        int row = idx >> 4, ch = idx & 15;
        uint32_t dsw = SWZ256((uint32_t)(row * 256 + ch * 16));
        const char* srch = (const char*)qhp + (size_t)(q0 + row) * (D_MODEL * 2) + (size_t)ch * 16;
        const char* srcl = (const char*)qlp + (size_t)(q0 + row) * (D_MODEL * 2) + (size_t)ch * 16;
        cp16(sb + FA_QHI + dsw, srch);
        cp16(sb + FA_QLO + dsw, srcl);
    }
    cp_commit();
    fa_issue_stage(sb, 0, 0, tid, kp, vp);
    fa_issue_stage(sb, 1, FAK, tid, kp, vp);

    const int g8 = lane >> 3;
    const int r8 = lane & 7;
    const int rowoff = (g8 & 1) * 8 + r8;
    const int qsel = g8 >> 1;

    float oacc[16][4];
#pragma unroll
    for (int t = 0; t < 16; t++) {
#pragma unroll
        for (int e = 0; e < 4; e++) { oacc[t][e] = 0.f; }
    }
    float m0 = -1e30f, m1 = -1e30f, l0 = 0.f, l1 = 0.f;
    const float sm_scale = 0.08838834764831843f;

    const int lrow0 = q0 + w * 16 + (lane >> 2);
    const int lcolb = (lane & 3) * 2;

    for (int kt = 0; kt < n_kt; kt++) {
        const int s = kt & 1;
        const int k0 = kt * FAK;
        CP_WAIT(1);
        __syncthreads();
        const uint32_t stg = sb + FA_STG + (uint32_t)s * FA_STAGE;

        float sacc[4][4];
#pragma unroll
        for (int t = 0; t < 4; t++) {
#pragma unroll
            for (int e = 0; e < 4; e++) { sacc[t][e] = 0.f; }
        }
#pragma unroll
        for (int ks = 0; ks < 8; ks++) {
            const int quad = ks * 2 + qsel;
            uint32_t qfh[4], qfl[4];
            const uint32_t qoff = SWZ256((uint32_t)((w * 16 + rowoff) * 256 + quad * 16));
            ldsm_x4(qfh, sb + FA_QHI + qoff);
            ldsm_x4(qfl, sb + FA_QLO + qoff);
#pragma unroll
            for (int nt = 0; nt < 2; nt++) {
                const uint32_t koff = SWZ256((uint32_t)((nt * 16 + rowoff) * 256 + quad * 16));
                uint32_t tk[4];
                ldsm_x4(tk, stg + koff);
                uint32_t b0[2], b1[2];
                b0[0] = tk[0]; b0[1] = tk[2];
                b1[0] = tk[1]; b1[1] = tk[3];
                mma_f16(sacc[nt * 2],     qfh, b0);
                mma_f16(sacc[nt * 2],     qfl, b0);
                mma_f16(sacc[nt * 2 + 1], qfh, b1);
                mma_f16(sacc[nt * 2 + 1], qfl, b1);
            }
        }

        const int need_mask = (k0 + FAK - 1 > q0 + w * 16) ? 1 : 0;
#pragma unroll
        for (int t = 0; t < 4; t++) {
#pragma unroll
            for (int e = 0; e < 4; e++) {
                float sv = sacc[t][e] * sm_scale;
                if (need_mask) {
                    int col = k0 + t * 8 + lcolb + (e & 1);
                    int row = lrow0 + ((e >> 1) & 1) * 8;
                    if (col > row) { sv = -1e30f; }
                }
                sacc[t][e] = sv;
            }
        }

        float rm0 = sacc[0][0], rm1 = sacc[0][2];
#pragma unroll
        for (int t = 0; t < 4; t++) {
            rm0 = fmaxf(rm0, fmaxf(sacc[t][0], sacc[t][1]));
            rm1 = fmaxf(rm1, fmaxf(sacc[t][2], sacc[t][3]));
        }
        rm0 = fmaxf(rm0, __shfl_xor_sync(0xffffffffu, rm0, 1));
        rm0 = fmaxf(rm0, __shfl_xor_sync(0xffffffffu, rm0, 2));
        rm1 = fmaxf(rm1, __shfl_xor_sync(0xffffffffu, rm1, 1));
        rm1 = fmaxf(rm1, __shfl_xor_sync(0xffffffffu, rm1, 2));
        float mn0 = fmaxf(m0, rm0);
        float mn1 = fmaxf(m1, rm1);
        float alpha0 = expf(m0 - mn0);
        float alpha1 = expf(m1 - mn1);
        float rs0 = 0.f, rs1 = 0.f;
#pragma unroll
        for (int t = 0; t < 4; t++) {
            float p0 = expf(sacc[t][0] - mn0);
            float p1 = expf(sacc[t][1] - mn0);
            float p2 = expf(sacc[t][2] - mn1);
            float p3 = expf(sacc[t][3] - mn1);
            rs0 += p0 + p1;
            rs1 += p2 + p3;
            sacc[t][0] = p0; sacc[t][1] = p1;
            sacc[t][2] = p2; sacc[t][3] = p3;
        }
        rs0 += __shfl_xor_sync(0xffffffffu, rs0, 1);
        rs0 += __shfl_xor_sync(0xffffffffu, rs0, 2);
        rs1 += __shfl_xor_sync(0xffffffffu, rs1, 1);
        rs1 += __shfl_xor_sync(0xffffffffu, rs1, 2);
        l0 = l0 * alpha0 + rs0;
        l1 = l1 * alpha1 + rs1;
        m0 = mn0; m1 = mn1;
#pragma unroll
        for (int t = 0; t < 16; t++) {
            oacc[t][0] *= alpha0; oacc[t][1] *= alpha0;
            oacc[t][2] *= alpha1; oacc[t][3] *= alpha1;
        }

        uint32_t pf[2][4];
#pragma unroll
        for (int j = 0; j < 2; j++) {
#pragma unroll
            for (int idx = 0; idx < 4; idx++) {
                int st = 2 * j + (idx >> 1);
                int rp = (idx & 1) * 2;
                __half p0 = __float2half_rn(sacc[st][rp]);
                __half p1 = __float2half_rn(sacc[st][rp + 1]);
                pf[j][idx] = (uint32_t)__half_as_ushort(p0)
                           | ((uint32_t)__half_as_ushort(p1) << 16);
            }
        }

        const int vrow_base = (lane & 7) + ((lane >> 3) & 1) * 8;
        const int vcol_base = ((lane >> 4) & 1) * 16;
#pragma unroll
        for (int j = 0; j < 2; j++) {
#pragma unroll
            for (int nt = 0; nt < 8; nt++) {
                const int vr = j * 16 + vrow_base;
                const int vcb = nt * 32 + vcol_base;
                const uint32_t voff = SWZ256((uint32_t)(vr * 256 + vcb));
                uint32_t tv[4];
                ldsm_x4_t(tv, stg + FA_TILE + voff);
                uint32_t b0[2], b1[2];
                b0[0] = tv[0]; b0[1] = tv[1];
                b1[0] = tv[2]; b1[1] = tv[3];
                mma_f16(oacc[nt * 2],     pf[j], b0);
                mma_f16(oacc[nt * 2 + 1], pf[j], b1);
            }
        }

        __syncthreads();
        if (kt + 2 < n_kt) {
            fa_issue_stage(sb, s, (kt + 2) * FAK, tid, kp, vp);
        } else {
            cp_commit();
        }
    }

    // ---- epilogue: normalize, store fp16 o ----
    const float inv0 = 1.f / l0;
    const float inv1 = 1.f / l1;
#pragma unroll
    for (int t = 0; t < 16; t++) {
        const int col = t * 8 + lcolb;
        const size_t off0 = (size_t)lrow0 * D_MODEL + col;
        const size_t off1 = (size_t)(lrow0 + 8) * D_MODEL + col;
        ushort2 a, bq;
        a.x = __half_as_ushort(__float2half_rn(oacc[t][0] * inv0));
        a.y = __half_as_ushort(__float2half_rn(oacc[t][1] * inv0));
        bq.x = __half_as_ushort(__float2half_rn(oacc[t][2] * inv1));
        bq.y = __half_as_ushort(__float2half_rn(oacc[t][3] * inv1));
        ((ushort2*)oph)[off0 >> 1] = a;
        ((ushort2*)oph)[off1 >> 1] = bq;
    }
}

// ======================= host side =======================
extern "C" void kernel_launch(void* const* d_in, const int* in_sizes, int n_in,
                              void* d_out, int out_size) {
    const float* x  = (const float*)d_in[0];
    const float* wq = (const float*)d_in[1];
    const float* wk = (const float*)d_in[2];
    const float* wv = (const float*)d_in[3];
    const float* wo = (const float*)d_in[4];
    float* out = (float*)d_out;

    __half *x16, *o16, *wq16, *wk16, *wv16, *wo16;
    cudaGetSymbolAddress((void**)&x16, g_x16);
    cudaGetSymbolAddress((void**)&o16, g_o16);
    cudaGetSymbolAddress((void**)&wq16, g_wq16);
    cudaGetSymbolAddress((void**)&wk16, g_wk16);
    cudaGetSymbolAddress((void**)&wv16, g_wv16);
    cudaGetSymbolAddress((void**)&wo16, g_wo16);

    rope_table_kernel<<<(S_LEN * (HD / 2) + 255) / 256, 256>>>();

    const int xn4 = MROWS * D_MODEL / 4;
    const int wn4 = D_MODEL * D_MODEL / 4;
    cvt_f16_kernel<<<(xn4 + 255) / 256, 256>>>(x, x16, xn4);
    cvt_f16_kernel<<<(wn4 + 255) / 256, 256>>>(wq, wq16, wn4);
    cvt_f16_kernel<<<(wn4 + 255) / 256, 256>>>(wk, wk16, wn4);
    cvt_f16_kernel<<<(wn4 + 255) / 256, 256>>>(wv, wv16, wn4);
    cvt_f16_kernel<<<(wn4 + 255) / 256, 256>>>(wo, wo16, wn4);

    cudaFuncSetAttribute(gemm_qkv, cudaFuncAttributeMaxDynamicSharedMemorySize, GEMM_SMEM);
    cudaFuncSetAttribute(gemm_out, cudaFuncAttributeMaxDynamicSharedMemorySize, GEMM_SMEM);

    gemm_qkv<<<dim3(48, MROWS / GBM), 256, GEMM_SMEM>>>(x16);

    cudaFuncSetAttribute(flash_attn_mma, cudaFuncAttributeMaxDynamicSharedMemorySize, FA_SMEM);
    flash_attn_mma<<<dim3(S_LEN / FAQ, B_SZ * NH), 128, FA_SMEM>>>();

    gemm_out<<<dim3(16, MROWS / GBM), 256, GEMM_SMEM>>>(o16, wo16, out);
}